// round 13
// baseline (speedup 1.0000x reference)
#include <cuda_runtime.h>
#include <cuda_fp16.h>
#include <math.h>

// Problem constants
#define BSZ   2
#define CC    256
#define NN    4096          // H*W
#define HEADS 8
#define HD    32
#define BA    8             // BSZ*AREA
#define NA    1024          // NN/AREA
#define MLPD  307

#define QKV_BSTRIDE (768*NN)
#define C_BSTRIDE   (CC*NN)

// ---------------- scratch ----------------------------------------------------
__device__ float g_qkv[BSZ * 768 * NN];
__device__ float g_pe [BSZ * CC  * NN];
__device__ float g_att[BSZ * CC  * NN];
__device__ float g_x1 [BSZ * CC  * NN];
__device__ float g_m  [BSZ * MLPD* NN];

// ---------------- helpers -----------------------------------------------------
__device__ __forceinline__ float ex2(float x) {
    float r;
    asm("ex2.approx.ftz.f32 %0, %1;" : "=f"(r) : "f"(x));
    return r;
}
__device__ __forceinline__ unsigned smem_u32(const void* p) {
    return (unsigned)__cvta_generic_to_shared(p);
}
__device__ __forceinline__ void ldsm4(unsigned* r, unsigned addr) {
    asm volatile("ldmatrix.sync.aligned.m8n8.x4.shared.b16 {%0,%1,%2,%3}, [%4];"
        : "=r"(r[0]), "=r"(r[1]), "=r"(r[2]), "=r"(r[3]) : "r"(addr));
}
__device__ __forceinline__ void ldsm4t(unsigned* r, unsigned addr) {
    asm volatile("ldmatrix.sync.aligned.m8n8.x4.trans.shared.b16 {%0,%1,%2,%3}, [%4];"
        : "=r"(r[0]), "=r"(r[1]), "=r"(r[2]), "=r"(r[3]) : "r"(addr));
}
__device__ __forceinline__ void mma16816(float* c, const unsigned* a,
                                         unsigned b0, unsigned b1) {
    asm volatile("mma.sync.aligned.m16n8k16.row.col.f32.f16.f16.f32 "
        "{%0,%1,%2,%3},{%4,%5,%6,%7},{%8,%9},{%0,%1,%2,%3};"
        : "+f"(c[0]), "+f"(c[1]), "+f"(c[2]), "+f"(c[3])
        : "r"(a[0]), "r"(a[1]), "r"(a[2]), "r"(a[3]), "r"(b0), "r"(b1));
}
__device__ __forceinline__ unsigned pkh2(float a, float b) {
    __half2 h = __floats2half2_rn(a, b);
    return *(unsigned*)&h;
}

// ---- conv1x1 GEMM via HMMA: 128m x 64n CTA tile, 8 warps (32m x 32n each) ---
// C[b][m][n] = epi((sum_k A[m][k]*(Bm[b][k][n](+B2))) * sc[m] + bi[m]) (+ res)
#define BKK 32
#define AP  (BKK + 8)      // As row pitch (halves)
#define BP  (64 + 8)       // Bs row pitch (halves)

__global__ __launch_bounds__(256, 2)
void gemm_kernel(const float* __restrict__ A,
                 const float* __restrict__ Bm,
                 const float* __restrict__ B2,
                 const float* __restrict__ sc,
                 const float* __restrict__ bi,
                 const float* __restrict__ res,
                 float* __restrict__ Cout,
                 int M, int K,
                 long sB, long sC, long sR, int epi)
{
    __shared__ __align__(16) __half As[2][128][AP];   // 20.5 KB
    __shared__ __align__(16) __half Bs[2][BKK][BP];   // 9.2 KB

    const int b = blockIdx.z;
    const float* Bb  = Bm + (long)b * sB;
    const float* B2b = B2 ? (B2 + (long)b * sB) : nullptr;
    const float* Rb  = res ? (res + (long)b * sR) : nullptr;
    float* Cb = Cout + (long)b * sC;

    const int m0 = blockIdx.y * 128;
    const int n0 = blockIdx.x * 64;
    const int tid  = threadIdx.x;
    const int lane = tid & 31;
    const int wid  = tid >> 5;
    const int wm = (wid >> 1) * 32;       // 0/32/64/96
    const int wn = (wid & 1) * 32;        // 0/32

    // loader indices
    const int am = tid >> 1;              // 0..127
    const int ak = (tid & 1) * 16;        // 0 or 16
    const int bk = tid >> 3;              // 0..31
    const int bn = (tid & 7) * 8;         // 0..56

    const bool k_vec = ((K & 3) == 0);
    const int nkt = (K + BKK - 1) / BKK;

    float acc[2][4][4] = {};              // mi x ni x frag
    uint4 apk[2], bpk;                    // fp16-packed prefetch

    #define LOAD_TILE(KT)                                                      \
    {                                                                          \
        const int k0 = (KT) * BKK;                                             \
        const int gm = m0 + am;                                                \
        float t[16];                                                           \
        _Pragma("unroll") for (int i = 0; i < 16; i++) t[i] = 0.f;             \
        if (gm < M) {                                                          \
            if (k_vec && (k0 + ak + 15 < K)) {                                 \
                _Pragma("unroll") for (int q4 = 0; q4 < 4; q4++) {             \
                    const float4 v = *(const float4*)(A + (long)gm * K + k0 + ak + 4 * q4); \
                    t[4*q4]=v.x; t[4*q4+1]=v.y; t[4*q4+2]=v.z; t[4*q4+3]=v.w;  \
                }                                                              \
            } else {                                                           \
                _Pragma("unroll") for (int i = 0; i < 16; i++) {               \
                    const int gk = k0 + ak + i;                                \
                    if (gk < K) t[i] = A[(long)gm * K + gk];                   \
                }                                                              \
            }                                                                  \
        }                                                                      \
        {                                                                      \
            __half h[16];                                                      \
            _Pragma("unroll") for (int i = 0; i < 16; i++) h[i] = __float2half_rn(t[i]); \
            apk[0] = *(uint4*)&h[0]; apk[1] = *(uint4*)&h[8];                  \
        }                                                                      \
        const int gk = k0 + bk;                                                \
        _Pragma("unroll") for (int i = 0; i < 8; i++) t[i] = 0.f;              \
        if (gk < K) {                                                          \
            const float* p = Bb + (long)gk * NN + n0 + bn;                     \
            _Pragma("unroll") for (int q4 = 0; q4 < 2; q4++) {                 \
                const float4 v = *(const float4*)(p + 4 * q4);                 \
                t[4*q4]=v.x; t[4*q4+1]=v.y; t[4*q4+2]=v.z; t[4*q4+3]=v.w;      \
            }                                                                  \
            if (B2b) {                                                         \
                const float* q = B2b + (long)gk * NN + n0 + bn;                \
                _Pragma("unroll") for (int q4 = 0; q4 < 2; q4++) {             \
                    const float4 w = *(const float4*)(q + 4 * q4);             \
                    t[4*q4]+=w.x; t[4*q4+1]+=w.y; t[4*q4+2]+=w.z; t[4*q4+3]+=w.w; \
                }                                                              \
            }                                                                  \
        }                                                                      \
        {                                                                      \
            __half h[8];                                                       \
            _Pragma("unroll") for (int i = 0; i < 8; i++) h[i] = __float2half_rn(t[i]); \
            bpk = *(uint4*)&h[0];                                              \
        }                                                                      \
    }

    #define STORE_TILE(BUF)                                                    \
    {                                                                          \
        *(uint4*)&As[BUF][am][ak]     = apk[0];                                \
        *(uint4*)&As[BUF][am][ak + 8] = apk[1];                                \
        *(uint4*)&Bs[BUF][bk][bn]     = bpk;                                   \
    }

    LOAD_TILE(0)
    STORE_TILE(0)
    __syncthreads();

    for (int kt = 0; kt < nkt; kt++) {
        const int buf = kt & 1;
        const bool more = (kt + 1 < nkt);
        if (more) LOAD_TILE(kt + 1)

        #pragma unroll
        for (int ks = 0; ks < BKK; ks += 16) {
            unsigned afr[2][4], bfr[2][4];
            #pragma unroll
            for (int mi = 0; mi < 2; mi++) {
                const unsigned addr = smem_u32(
                    &As[buf][wm + mi * 16 + (lane & 15)][ks + (lane >> 4) * 8]);
                ldsm4(afr[mi], addr);
            }
            #pragma unroll
            for (int g = 0; g < 2; g++) {
                const int row = ks + (lane & 15);
                const int col = wn + g * 16 + ((lane >> 4) * 8);
                ldsm4t(bfr[g], smem_u32(&Bs[buf][row][col]));
            }
            #pragma unroll
            for (int mi = 0; mi < 2; mi++)
                #pragma unroll
                for (int g = 0; g < 2; g++) {
                    mma16816(acc[mi][2 * g],     afr[mi], bfr[g][0], bfr[g][1]);
                    mma16816(acc[mi][2 * g + 1], afr[mi], bfr[g][2], bfr[g][3]);
                }
        }
        if (more) {
            STORE_TILE(buf ^ 1)
            __syncthreads();
        }
    }

    // epilogue: c-frag (m16n8.f32): regs 0/1 -> (row, col..col+1), 2/3 -> row+8
    #pragma unroll
    for (int mi = 0; mi < 2; mi++) {
        #pragma unroll
        for (int hh = 0; hh < 2; hh++) {
            const int m = m0 + wm + mi * 16 + (lane >> 2) + hh * 8;
            if (m >= M) continue;
            const float scl = sc[m], bia = bi[m];
            #pragma unroll
            for (int ni = 0; ni < 4; ni++) {
                float v0 = acc[mi][ni][2 * hh]     * scl + bia;
                float v1 = acc[mi][ni][2 * hh + 1] * scl + bia;
                if (epi == 1) {
                    v0 = v0 / (1.f + __expf(-v0));
                    v1 = v1 / (1.f + __expf(-v1));
                }
                const int n = n0 + wn + ni * 8 + (lane & 3) * 2;
                const long base = (long)m * NN + n;
                if (Rb) {
                    const float2 r = *(const float2*)(Rb + base);
                    v0 += r.x; v1 += r.y;
                }
                *(float2*)(Cb + base) = make_float2(v0, v1);
            }
        }
    }
    #undef LOAD_TILE
    #undef STORE_TILE
}

// ---------------- depthwise 3x3 ----------------------------------------------
__global__ void dwconv_kernel(const float* __restrict__ w_pe,
                              const float* __restrict__ s,
                              const float* __restrict__ bi)
{
    const int bc = blockIdx.y;
    const int b = bc >> 8, c = bc & 255;
    const int hw = blockIdx.x * 256 + threadIdx.x;
    const int h = hw >> 6, w = hw & 63;
    const float* src = g_qkv + (long)b * QKV_BSTRIDE + (long)(512 + c) * NN;
    float acc = 0.f;
    #pragma unroll
    for (int kh = 0; kh < 3; kh++) {
        const int hh = h + kh - 1;
        if (hh < 0 || hh >= 64) continue;
        #pragma unroll
        for (int kw = 0; kw < 3; kw++) {
            const int ww = w + kw - 1;
            if (ww < 0 || ww >= 64) continue;
            acc += src[hh * 64 + ww] * w_pe[c * 9 + kh * 3 + kw];
        }
    }
    g_pe[(long)b * C_BSTRIDE + (long)c * NN + hw] = acc * s[c] + bi[c];
}

// ---- area attention via HMMA (identical to R11 — verified 48us) --------------
#define PITCH 136    // halves per smem row (272B: 16B-divisible, bank-clean)

__global__ __launch_bounds__(256)
void attn_kernel()
{
    __shared__ __align__(16) __half Qs[32][PITCH];
    __shared__ __align__(16) __half Ks[32][PITCH];
    __shared__ __align__(16) __half Vs[32][PITCH];

    const int ba = blockIdx.y >> 3;
    const int h  = blockIdx.y & 7;
    const int q0 = blockIdx.x * 128;
    const int tid  = threadIdx.x;
    const int lane = tid & 31;
    const int wid  = tid >> 5;
    const int wq   = wid * 16;

    const float scale = 0.17677669529663687f * 1.4426950408889634f;

    const long qflat0 = (long)ba * 524288 + (long)(h * HD) * 1024;
    const long kflat0 = qflat0 + 256 * 1024;
    const long vflat0 = (long)ba * 262144 + (long)(h * HD) * 1024;

    const int fd = tid >> 3;
    const int fg = (tid & 7) * 16;

    {
        const long f = qflat0 + (long)fd * 1024 + q0 + fg;
        const float* src = &g_qkv[(f >> 21) * QKV_BSTRIDE + (f & 2097151)];
        __half t[16];
        #pragma unroll
        for (int i = 0; i < 4; i++) {
            const float4 v = *(const float4*)(src + 4 * i);
            t[4*i+0] = __float2half_rn(v.x * scale);
            t[4*i+1] = __float2half_rn(v.y * scale);
            t[4*i+2] = __float2half_rn(v.z * scale);
            t[4*i+3] = __float2half_rn(v.w * scale);
        }
        *(uint4*)&Qs[fd][fg]     = *(uint4*)&t[0];
        *(uint4*)&Qs[fd][fg + 8] = *(uint4*)&t[8];
    }
    __syncthreads();

    unsigned aq[2][4];
    #pragma unroll
    for (int dc = 0; dc < 2; dc++) {
        const int row = dc * 16 + (lane & 7) + ((lane >> 4) & 1) * 8;
        const int col = wq + ((lane >> 3) & 1) * 8;
        ldsm4t(aq[dc], smem_u32(&Qs[row][col]));
    }

    float oacc[4][4] = {};
    float lsum0 = 0.f, lsum1 = 0.f;

    for (int m0 = 0; m0 < NA; m0 += 128) {
        __syncthreads();
        {
            const long fk = kflat0 + (long)fd * 1024 + m0 + fg;
            const float* sk = &g_qkv[(fk >> 21) * QKV_BSTRIDE + (fk & 2097151)];
            __half t[16];
            #pragma unroll
            for (int i = 0; i < 4; i++) {
                const float4 v = *(const float4*)(sk + 4 * i);
                t[4*i+0] = __float2half_rn(v.x);
                t[4*i+1] = __float2half_rn(v.y);
                t[4*i+2] = __float2half_rn(v.z);
                t[4*i+3] = __float2half_rn(v.w);
            }
            *(uint4*)&Ks[fd][fg]     = *(uint4*)&t[0];
            *(uint4*)&Ks[fd][fg + 8] = *(uint4*)&t[8];

            const long fv = vflat0 + (long)fd * 1024 + m0 + fg;
            const float* sv = &g_qkv[(fv >> 20) * QKV_BSTRIDE + 512 * NN + (fv & 1048575)];
            #pragma unroll
            for (int i = 0; i < 4; i++) {
                const float4 v = *(const float4*)(sv + 4 * i);
                t[4*i+0] = __float2half_rn(v.x);
                t[4*i+1] = __float2half_rn(v.y);
                t[4*i+2] = __float2half_rn(v.z);
                t[4*i+3] = __float2half_rn(v.w);
            }
            *(uint4*)&Vs[fd][fg]     = *(uint4*)&t[0];
            *(uint4*)&Vs[fd][fg + 8] = *(uint4*)&t[8];
        }
        __syncthreads();

        float sacc[16][4];
        #pragma unroll
        for (int nt = 0; nt < 16; nt++) {
            sacc[nt][0] = 0.f; sacc[nt][1] = 0.f;
            sacc[nt][2] = 0.f; sacc[nt][3] = 0.f;
        }
        #pragma unroll
        for (int dc = 0; dc < 2; dc++) {
            #pragma unroll
            for (int ntp = 0; ntp < 8; ntp++) {
                unsigned bk[4];
                const int row = dc * 16 + (lane & 7) + ((lane >> 3) & 1) * 8;
                const int col = ntp * 16 + ((lane >> 4) & 1) * 8;
                ldsm4t(bk, smem_u32(&Ks[row][col]));
                mma16816(sacc[2 * ntp],     aq[dc], bk[0], bk[1]);
                mma16816(sacc[2 * ntp + 1], aq[dc], bk[2], bk[3]);
            }
        }
        #pragma unroll
        for (int nt = 0; nt < 16; nt++) {
            sacc[nt][0] = ex2(sacc[nt][0]);
            sacc[nt][1] = ex2(sacc[nt][1]);
            sacc[nt][2] = ex2(sacc[nt][2]);
            sacc[nt][3] = ex2(sacc[nt][3]);
            lsum0 += sacc[nt][0] + sacc[nt][1];
            lsum1 += sacc[nt][2] + sacc[nt][3];
        }
        #pragma unroll
        for (int kt = 0; kt < 8; kt++) {
            unsigned pa[4];
            pa[0] = pkh2(sacc[2 * kt][0],     sacc[2 * kt][1]);
            pa[1] = pkh2(sacc[2 * kt][2],     sacc[2 * kt][3]);
            pa[2] = pkh2(sacc[2 * kt + 1][0], sacc[2 * kt + 1][1]);
            pa[3] = pkh2(sacc[2 * kt + 1][2], sacc[2 * kt + 1][3]);
            #pragma unroll
            for (int dtp = 0; dtp < 2; dtp++) {
                unsigned bv[4];
                const int row = dtp * 16 + (lane & 7) + ((lane >> 4) & 1) * 8;
                const int col = kt * 16 + ((lane >> 3) & 1) * 8;
                ldsm4(bv, smem_u32(&Vs[row][col]));
                mma16816(oacc[2 * dtp],     pa, bv[0], bv[1]);
                mma16816(oacc[2 * dtp + 1], pa, bv[2], bv[3]);
            }
        }
    }

    lsum0 += __shfl_xor_sync(0xffffffff, lsum0, 1);
    lsum0 += __shfl_xor_sync(0xffffffff, lsum0, 2);
    lsum1 += __shfl_xor_sync(0xffffffff, lsum1, 1);
    lsum1 += __shfl_xor_sync(0xffffffff, lsum1, 2);
    const float inv0 = 1.f / lsum0;
    const float inv1 = 1.f / lsum1;

    const int qg = q0 + wq + (lane >> 2);
    #pragma unroll
    for (int dt = 0; dt < 4; dt++) {
        const int d = dt * 8 + (lane & 3) * 2;
        #pragma unroll
        for (int e = 0; e < 2; e++) {
            const long f0 = vflat0 + (long)(d + e) * 1024 + qg;
            g_att[(f0 >> 20) * C_BSTRIDE + (f0 & 1048575)] = oacc[dt][e] * inv0;
            const long f1 = f0 + 8;
            g_att[(f1 >> 20) * C_BSTRIDE + (f1 & 1048575)] = oacc[dt][2 + e] * inv1;
        }
    }
}

// ---------------- launch -------------------------------------------------------
extern "C" void kernel_launch(void* const* d_in, const int* in_sizes, int n_in,
                              void* d_out, int out_size)
{
    const float* x      = (const float*)d_in[0];
    const float* w_qk   = (const float*)d_in[1];
    const float* s_qk   = (const float*)d_in[2];
    const float* b_qk   = (const float*)d_in[3];
    const float* w_v    = (const float*)d_in[4];
    const float* s_v    = (const float*)d_in[5];
    const float* b_v    = (const float*)d_in[6];
    const float* w_pe   = (const float*)d_in[7];
    const float* s_pe   = (const float*)d_in[8];
    const float* b_pe   = (const float*)d_in[9];
    const float* w_proj = (const float*)d_in[10];
    const float* s_proj = (const float*)d_in[11];
    const float* b_proj = (const float*)d_in[12];
    const float* w_m1   = (const float*)d_in[13];
    const float* s_m1   = (const float*)d_in[14];
    const float* b_m1   = (const float*)d_in[15];
    const float* w_m2   = (const float*)d_in[16];
    const float* s_m2   = (const float*)d_in[17];
    const float* b_m2   = (const float*)d_in[18];
    float* out = (float*)d_out;

    float *qkv, *pe, *att, *x1, *mb;
    cudaGetSymbolAddress((void**)&qkv, g_qkv);
    cudaGetSymbolAddress((void**)&pe,  g_pe);
    cudaGetSymbolAddress((void**)&att, g_att);
    cudaGetSymbolAddress((void**)&x1,  g_x1);
    cudaGetSymbolAddress((void**)&mb,  g_m);

    // qk -> g_qkv channels [0,512)   (512 blocks)
    gemm_kernel<<<dim3(64, 4, BSZ), 256>>>(w_qk, x, nullptr, s_qk, b_qk, nullptr,
        qkv, 512, 256, (long)C_BSTRIDE, (long)QKV_BSTRIDE, 0, 0);
    // v -> g_qkv channels [512,768)  (256 blocks)
    gemm_kernel<<<dim3(64, 2, BSZ), 256>>>(w_v, x, nullptr, s_v, b_v, nullptr,
        qkv + 512 * NN, 256, 256, (long)C_BSTRIDE, (long)QKV_BSTRIDE, 0, 0);
    // pe = dwconv3x3(v)
    dwconv_kernel<<<dim3(16, BSZ * CC), 256>>>(w_pe, s_pe, b_pe);
    // area attention -> g_att
    attn_kernel<<<dim3(NA / 128, BA * HEADS), 256>>>();
    // x1 = x + conv1x1(att + pe, w_proj)   (256 blocks)
    gemm_kernel<<<dim3(64, 2, BSZ), 256>>>(w_proj, att, pe, s_proj, b_proj, x,
        x1, 256, 256, (long)C_BSTRIDE, (long)C_BSTRIDE, (long)C_BSTRIDE, 0);
    // m = silu(conv1x1(x1, w_m1))          (384 blocks)
    gemm_kernel<<<dim3(64, 3, BSZ), 256>>>(w_m1, x1, nullptr, s_m1, b_m1, nullptr,
        mb, MLPD, 256, (long)C_BSTRIDE, (long)MLPD * NN, 0, 1);
    // out = x1 + conv1x1(m, w_m2)          (256 blocks, K=307)
    gemm_kernel<<<dim3(64, 2, BSZ), 256>>>(w_m2, mb, nullptr, s_m2, b_m2, x1,
        out, 256, MLPD, (long)MLPD * NN, (long)C_BSTRIDE, (long)C_BSTRIDE, 0);
}

// round 14
// speedup vs baseline: 1.4497x; 1.4497x over previous
#include <cuda_runtime.h>
#include <cuda_fp16.h>
#include <math.h>

// Problem constants
#define BSZ   2
#define CC    256
#define NN    4096
#define HEADS 8
#define HD    32
#define BA    8
#define NA    1024
#define MLPD  307
#define MLPD_PAD 320
#define M1_PAD   384

#define QKV_BSTRIDE (768*NN)
#define C_BSTRIDE   (CC*NN)
#define MH_BSTRIDE  (MLPD_PAD*NN)

// ---------------- scratch ----------------------------------------------------
__device__ float  g_x1  [BSZ*CC*NN];          // fp32 residual for final add
__device__ __half g_xh  [BSZ*CC*NN];
__device__ __half g_qkvh[BSZ*768*NN];
__device__ __half g_atth[BSZ*CC*NN];
__device__ __half g_aph [BSZ*CC*NN];          // att + pe (proj B input)
__device__ __half g_x1h [BSZ*CC*NN];
__device__ __half g_mh  [BSZ*MLPD_PAD*NN];    // pad rows zeroed by prep
__device__ __half g_wqkvh[768*256];
__device__ __half g_wprojh[256*256];
__device__ __half g_wm1h[M1_PAD*256];         // pad rows zeroed
__device__ __half g_wm2h[256*MLPD_PAD];       // pad cols zeroed
__device__ float  g_sqkvf[768];
__device__ float  g_bqkvf[768];

// ---------------- helpers -----------------------------------------------------
__device__ __forceinline__ float ex2(float x) {
    float r;
    asm("ex2.approx.ftz.f32 %0, %1;" : "=f"(r) : "f"(x));
    return r;
}
__device__ __forceinline__ unsigned smem_u32(const void* p) {
    return (unsigned)__cvta_generic_to_shared(p);
}
__device__ __forceinline__ void cpa16(unsigned dst, const __half* src) {
    unsigned long long g = (unsigned long long)__cvta_generic_to_global((const void*)src);
    asm volatile("cp.async.cg.shared.global [%0], [%1], 16;" :: "r"(dst), "l"(g) : "memory");
}
__device__ __forceinline__ void ldsm4(unsigned* r, unsigned addr) {
    asm volatile("ldmatrix.sync.aligned.m8n8.x4.shared.b16 {%0,%1,%2,%3}, [%4];"
        : "=r"(r[0]), "=r"(r[1]), "=r"(r[2]), "=r"(r[3]) : "r"(addr));
}
__device__ __forceinline__ void ldsm4t(unsigned* r, unsigned addr) {
    asm volatile("ldmatrix.sync.aligned.m8n8.x4.trans.shared.b16 {%0,%1,%2,%3}, [%4];"
        : "=r"(r[0]), "=r"(r[1]), "=r"(r[2]), "=r"(r[3]) : "r"(addr));
}
__device__ __forceinline__ void mma16816(float* c, const unsigned* a,
                                         unsigned b0, unsigned b1) {
    asm volatile("mma.sync.aligned.m16n8k16.row.col.f32.f16.f16.f32 "
        "{%0,%1,%2,%3},{%4,%5,%6,%7},{%8,%9},{%0,%1,%2,%3};"
        : "+f"(c[0]), "+f"(c[1]), "+f"(c[2]), "+f"(c[3])
        : "r"(a[0]), "r"(a[1]), "r"(a[2]), "r"(a[3]), "r"(b0), "r"(b1));
}
__device__ __forceinline__ unsigned pkh2(float a, float b) {
    __half2 h = __floats2half2_rn(a, b);
    return *(unsigned*)&h;
}

// ---------------- prep: fp16 conversions + padding ----------------------------
__global__ void prep_kernel(const float* __restrict__ x,
                            const float* __restrict__ w_qk, const float* __restrict__ w_v,
                            const float* __restrict__ w_proj,
                            const float* __restrict__ w_m1, const float* __restrict__ w_m2,
                            const float* __restrict__ s_qk, const float* __restrict__ b_qk,
                            const float* __restrict__ s_v,  const float* __restrict__ b_v)
{
    const int S0 = BSZ*CC*NN;
    const int S1 = 768*256;
    const int S2 = 256*256;
    const int S3 = M1_PAD*256;
    const int S4 = 256*MLPD_PAD;
    const int S5 = BSZ*(MLPD_PAD-MLPD)*NN;
    const int S6 = 768;
    const int TOT = S0+S1+S2+S3+S4+S5+S6+S6;
    for (int i = blockIdx.x*blockDim.x + threadIdx.x; i < TOT; i += gridDim.x*blockDim.x) {
        int idx = i;
        if (idx < S0) { g_xh[idx] = __float2half_rn(x[idx]); continue; }
        idx -= S0;
        if (idx < S1) {
            g_wqkvh[idx] = __float2half_rn(idx < 512*256 ? w_qk[idx] : w_v[idx-512*256]);
            continue;
        }
        idx -= S1;
        if (idx < S2) { g_wprojh[idx] = __float2half_rn(w_proj[idx]); continue; }
        idx -= S2;
        if (idx < S3) {
            const int r = idx >> 8;
            g_wm1h[idx] = __float2half_rn(r < MLPD ? w_m1[idx] : 0.f);
            continue;
        }
        idx -= S3;
        if (idx < S4) {
            const int r = idx / MLPD_PAD, c = idx % MLPD_PAD;
            g_wm2h[idx] = __float2half_rn(c < MLPD ? w_m2[r*MLPD + c] : 0.f);
            continue;
        }
        idx -= S4;
        if (idx < S5) {
            const int b  = idx / ((MLPD_PAD-MLPD)*NN);
            const int rr = idx % ((MLPD_PAD-MLPD)*NN);
            g_mh[(long)b*MH_BSTRIDE + MLPD*NN + rr] = __float2half_rn(0.f);
            continue;
        }
        idx -= S5;
        if (idx < S6) { g_sqkvf[idx] = idx < 512 ? s_qk[idx] : s_v[idx-512]; continue; }
        idx -= S6;
        g_bqkvf[idx] = idx < 512 ? b_qk[idx] : b_v[idx-512];
    }
}

// ---- conv1x1 GEMM via HMMA + cp.async: 128m x 128n, 8 warps (64m x 32n) ------
// A, B fp16 (padded: no guards). outputs fp32 and/or fp16.
#define BKK 32
#define AP  (BKK + 8)      // 40 halves = 80B rows (16B-divisible)
#define BP  (128 + 8)      // 136 halves = 272B rows

__global__ __launch_bounds__(256, 2)
void gemm_kernel(const __half* __restrict__ Ag_,
                 const __half* __restrict__ Bg_,
                 const float* __restrict__ res,
                 const float* __restrict__ sc,
                 const float* __restrict__ bi,
                 float* __restrict__ Cf_,
                 __half* __restrict__ Ch_,
                 int M, int K,
                 long sB, long sCf, long sCh, long sR, int epi)
{
    __shared__ __align__(16) __half As[2][128][AP];   // 20.5 KB
    __shared__ __align__(16) __half Bs[2][BKK][BP];   // 17.4 KB

    const int b = blockIdx.z;
    const __half* Ag = Ag_;
    const __half* Bg = Bg_ + (long)b * sB;
    const float*  Rb = res ? (res + (long)b * sR) : nullptr;
    float*  Cf = Cf_ ? (Cf_ + (long)b * sCf) : nullptr;
    __half* Ch = Ch_ ? (Ch_ + (long)b * sCh) : nullptr;

    const int m0 = blockIdx.y * 128;
    const int n0 = blockIdx.x * 128;
    const int tid  = threadIdx.x;
    const int lane = tid & 31;
    const int wid  = tid >> 5;
    const int wm = (wid >> 2) * 64;
    const int wn = (wid & 3) * 32;

    const int nkt = K / BKK;     // K always multiple of 32 (256 or 320)

    float acc[4][4][4] = {};

    #define ISSUE(KT)                                                          \
    {                                                                          \
        const int k0 = (KT) * BKK;                                             \
        const int st = (KT) & 1;                                               \
        const __half* ap = Ag + (long)(m0 + (tid >> 1)) * K + k0 + (tid & 1) * 16; \
        cpa16(smem_u32(&As[st][tid >> 1][(tid & 1) * 16]), ap);                \
        cpa16(smem_u32(&As[st][tid >> 1][(tid & 1) * 16 + 8]), ap + 8);        \
        const __half* bp = Bg + (long)(k0 + (tid >> 3)) * NN + n0 + (tid & 7) * 16; \
        cpa16(smem_u32(&Bs[st][tid >> 3][(tid & 7) * 16]), bp);                \
        cpa16(smem_u32(&Bs[st][tid >> 3][(tid & 7) * 16 + 8]), bp + 8);        \
        asm volatile("cp.async.commit_group;" ::: "memory");                   \
    }

    ISSUE(0)

    for (int kt = 0; kt < nkt; kt++) {
        if (kt + 1 < nkt) {
            ISSUE(kt + 1)
            asm volatile("cp.async.wait_group 1;" ::: "memory");
        } else {
            asm volatile("cp.async.wait_group 0;" ::: "memory");
        }
        __syncthreads();
        const int buf = kt & 1;
        #pragma unroll
        for (int ks = 0; ks < BKK; ks += 16) {
            unsigned afr[4][4], bfr[2][4];
            #pragma unroll
            for (int mi = 0; mi < 4; mi++) {
                const unsigned addr = smem_u32(
                    &As[buf][wm + mi * 16 + (lane & 15)][ks + (lane >> 4) * 8]);
                ldsm4(afr[mi], addr);
            }
            #pragma unroll
            for (int g = 0; g < 2; g++) {
                const int row = ks + (lane & 15);
                const int col = wn + g * 16 + ((lane >> 4) * 8);
                ldsm4t(bfr[g], smem_u32(&Bs[buf][row][col]));
            }
            #pragma unroll
            for (int mi = 0; mi < 4; mi++)
                #pragma unroll
                for (int g = 0; g < 2; g++) {
                    mma16816(acc[mi][2 * g],     afr[mi], bfr[g][0], bfr[g][1]);
                    mma16816(acc[mi][2 * g + 1], afr[mi], bfr[g][2], bfr[g][3]);
                }
        }
        __syncthreads();
    }
    #undef ISSUE

    // epilogue
    #pragma unroll
    for (int mi = 0; mi < 4; mi++) {
        #pragma unroll
        for (int hh = 0; hh < 2; hh++) {
            const int m = m0 + wm + mi * 16 + (lane >> 2) + hh * 8;
            if (m >= M) continue;
            const float scl = sc[m], bia = bi[m];
            #pragma unroll
            for (int ni = 0; ni < 4; ni++) {
                float v0 = acc[mi][ni][2 * hh]     * scl + bia;
                float v1 = acc[mi][ni][2 * hh + 1] * scl + bia;
                if (epi == 1) {
                    v0 = v0 / (1.f + __expf(-v0));
                    v1 = v1 / (1.f + __expf(-v1));
                }
                const int n = n0 + wn + ni * 8 + (lane & 3) * 2;
                const long base = (long)m * NN + n;
                if (Rb) {
                    const float2 r = *(const float2*)(Rb + base);
                    v0 += r.x; v1 += r.y;
                }
                if (Cf) *(float2*)(Cf + base) = make_float2(v0, v1);
                if (Ch) *(__half2*)(Ch + base) = __floats2half2_rn(v0, v1);
            }
        }
    }
}

// ---------------- depthwise 3x3 on v (fp16 in) + att add -> g_aph -------------
__global__ void dwconv_kernel(const float* __restrict__ w_pe,
                              const float* __restrict__ s,
                              const float* __restrict__ bi)
{
    const int bc = blockIdx.y;
    const int b = bc >> 8, c = bc & 255;
    const int hw = blockIdx.x * 256 + threadIdx.x;
    const int h = hw >> 6, w = hw & 63;
    const __half* src = g_qkvh + (long)b * QKV_BSTRIDE + (long)(512 + c) * NN;
    float acc = 0.f;
    #pragma unroll
    for (int kh = 0; kh < 3; kh++) {
        const int hh = h + kh - 1;
        if (hh < 0 || hh >= 64) continue;
        #pragma unroll
        for (int kw = 0; kw < 3; kw++) {
            const int ww = w + kw - 1;
            if (ww < 0 || ww >= 64) continue;
            acc += __half2float(src[hh * 64 + ww]) * w_pe[c * 9 + kh * 3 + kw];
        }
    }
    const long o = (long)b * C_BSTRIDE + (long)c * NN + hw;
    const float att = __half2float(g_atth[o]);
    g_aph[o] = __float2half_rn(acc * s[c] + bi[c] + att);
}

// ---- area attention via HMMA (R11 structure, fp16 qkv input) ------------------
#define PITCH 136

__global__ __launch_bounds__(256)
void attn_kernel()
{
    __shared__ __align__(16) __half Qs[32][PITCH];
    __shared__ __align__(16) __half Ks[32][PITCH];
    __shared__ __align__(16) __half Vs[32][PITCH];

    const int ba = blockIdx.y >> 3;
    const int h  = blockIdx.y & 7;
    const int q0 = blockIdx.x * 128;
    const int tid  = threadIdx.x;
    const int lane = tid & 31;
    const int wid  = tid >> 5;
    const int wq   = wid * 16;

    const float scale = 0.17677669529663687f * 1.4426950408889634f;

    const long qflat0 = (long)ba * 524288 + (long)(h * HD) * 1024;
    const long kflat0 = qflat0 + 256 * 1024;
    const long vflat0 = (long)ba * 262144 + (long)(h * HD) * 1024;

    const int fd = tid >> 3;
    const int fg = (tid & 7) * 16;

    // Q fill: fp16 in, scale in fp32 domain (same rounding as before)
    {
        const long f = qflat0 + (long)fd * 1024 + q0 + fg;
        const __half* src = &g_qkvh[(f >> 21) * QKV_BSTRIDE + (f & 2097151)];
        uint4 u0 = *(const uint4*)src;
        uint4 u1 = *(const uint4*)(src + 8);
        __half2* p0 = (__half2*)&u0;
        __half2* p1 = (__half2*)&u1;
        #pragma unroll
        for (int j = 0; j < 4; j++) {
            float2 f0 = __half22float2(p0[j]);
            p0[j] = __floats2half2_rn(f0.x * scale, f0.y * scale);
            float2 f1 = __half22float2(p1[j]);
            p1[j] = __floats2half2_rn(f1.x * scale, f1.y * scale);
        }
        *(uint4*)&Qs[fd][fg]     = u0;
        *(uint4*)&Qs[fd][fg + 8] = u1;
    }
    __syncthreads();

    unsigned aq[2][4];
    #pragma unroll
    for (int dc = 0; dc < 2; dc++) {
        const int row = dc * 16 + (lane & 7) + ((lane >> 4) & 1) * 8;
        const int col = wq + ((lane >> 3) & 1) * 8;
        ldsm4t(aq[dc], smem_u32(&Qs[row][col]));
    }

    float oacc[4][4] = {};
    float lsum0 = 0.f, lsum1 = 0.f;

    for (int m0 = 0; m0 < NA; m0 += 128) {
        __syncthreads();
        {
            const long fk = kflat0 + (long)fd * 1024 + m0 + fg;
            const __half* sk = &g_qkvh[(fk >> 21) * QKV_BSTRIDE + (fk & 2097151)];
            *(uint4*)&Ks[fd][fg]     = *(const uint4*)sk;
            *(uint4*)&Ks[fd][fg + 8] = *(const uint4*)(sk + 8);
            const long fv = vflat0 + (long)fd * 1024 + m0 + fg;
            const __half* sv = &g_qkvh[(fv >> 20) * QKV_BSTRIDE + 512 * NN + (fv & 1048575)];
            *(uint4*)&Vs[fd][fg]     = *(const uint4*)sv;
            *(uint4*)&Vs[fd][fg + 8] = *(const uint4*)(sv + 8);
        }
        __syncthreads();

        float sacc[16][4];
        #pragma unroll
        for (int nt = 0; nt < 16; nt++) {
            sacc[nt][0] = 0.f; sacc[nt][1] = 0.f;
            sacc[nt][2] = 0.f; sacc[nt][3] = 0.f;
        }
        #pragma unroll
        for (int dc = 0; dc < 2; dc++) {
            #pragma unroll
            for (int ntp = 0; ntp < 8; ntp++) {
                unsigned bk[4];
                const int row = dc * 16 + (lane & 7) + ((lane >> 3) & 1) * 8;
                const int col = ntp * 16 + ((lane >> 4) & 1) * 8;
                ldsm4t(bk, smem_u32(&Ks[row][col]));
                mma16816(sacc[2 * ntp],     aq[dc], bk[0], bk[1]);
                mma16816(sacc[2 * ntp + 1], aq[dc], bk[2], bk[3]);
            }
        }
        #pragma unroll
        for (int nt = 0; nt < 16; nt++) {
            sacc[nt][0] = ex2(sacc[nt][0]);
            sacc[nt][1] = ex2(sacc[nt][1]);
            sacc[nt][2] = ex2(sacc[nt][2]);
            sacc[nt][3] = ex2(sacc[nt][3]);
            lsum0 += sacc[nt][0] + sacc[nt][1];
            lsum1 += sacc[nt][2] + sacc[nt][3];
        }
        #pragma unroll
        for (int kt = 0; kt < 8; kt++) {
            unsigned pa[4];
            pa[0] = pkh2(sacc[2 * kt][0],     sacc[2 * kt][1]);
            pa[1] = pkh2(sacc[2 * kt][2],     sacc[2 * kt][3]);
            pa[2] = pkh2(sacc[2 * kt + 1][0], sacc[2 * kt + 1][1]);
            pa[3] = pkh2(sacc[2 * kt + 1][2], sacc[2 * kt + 1][3]);
            #pragma unroll
            for (int dtp = 0; dtp < 2; dtp++) {
                unsigned bv[4];
                const int row = dtp * 16 + (lane & 7) + ((lane >> 4) & 1) * 8;
                const int col = kt * 16 + ((lane >> 3) & 1) * 8;
                ldsm4(bv, smem_u32(&Vs[row][col]));
                mma16816(oacc[2 * dtp],     pa, bv[0], bv[1]);
                mma16816(oacc[2 * dtp + 1], pa, bv[2], bv[3]);
            }
        }
    }

    lsum0 += __shfl_xor_sync(0xffffffff, lsum0, 1);
    lsum0 += __shfl_xor_sync(0xffffffff, lsum0, 2);
    lsum1 += __shfl_xor_sync(0xffffffff, lsum1, 1);
    lsum1 += __shfl_xor_sync(0xffffffff, lsum1, 2);
    const float inv0 = 1.f / lsum0;
    const float inv1 = 1.f / lsum1;

    const int qg = q0 + wq + (lane >> 2);
    #pragma unroll
    for (int dt = 0; dt < 4; dt++) {
        const int d = dt * 8 + (lane & 3) * 2;
        #pragma unroll
        for (int e = 0; e < 2; e++) {
            const long f0 = vflat0 + (long)(d + e) * 1024 + qg;
            g_atth[(f0 >> 20) * C_BSTRIDE + (f0 & 1048575)] =
                __float2half_rn(oacc[dt][e] * inv0);
            const long f1 = f0 + 8;
            g_atth[(f1 >> 20) * C_BSTRIDE + (f1 & 1048575)] =
                __float2half_rn(oacc[dt][2 + e] * inv1);
        }
    }
}

// ---------------- launch -------------------------------------------------------
extern "C" void kernel_launch(void* const* d_in, const int* in_sizes, int n_in,
                              void* d_out, int out_size)
{
    const float* x      = (const float*)d_in[0];
    const float* w_qk   = (const float*)d_in[1];
    const float* s_qk   = (const float*)d_in[2];
    const float* b_qk   = (const float*)d_in[3];
    const float* w_v    = (const float*)d_in[4];
    const float* s_v    = (const float*)d_in[5];
    const float* b_v    = (const float*)d_in[6];
    const float* w_pe   = (const float*)d_in[7];
    const float* s_pe   = (const float*)d_in[8];
    const float* b_pe   = (const float*)d_in[9];
    const float* w_proj = (const float*)d_in[10];
    const float* s_proj = (const float*)d_in[11];
    const float* b_proj = (const float*)d_in[12];
    const float* w_m1   = (const float*)d_in[13];
    const float* s_m1   = (const float*)d_in[14];
    const float* b_m1   = (const float*)d_in[15];
    const float* w_m2   = (const float*)d_in[16];
    const float* s_m2   = (const float*)d_in[17];
    const float* b_m2   = (const float*)d_in[18];
    float* out = (float*)d_out;

    __half *xh, *qkvh, *aph, *x1h, *mh, *wqkvh, *wprojh, *wm1h, *wm2h;
    float *x1, *sqkv, *bqkv;
    cudaGetSymbolAddress((void**)&xh,    g_xh);
    cudaGetSymbolAddress((void**)&qkvh,  g_qkvh);
    cudaGetSymbolAddress((void**)&aph,   g_aph);
    cudaGetSymbolAddress((void**)&x1h,   g_x1h);
    cudaGetSymbolAddress((void**)&mh,    g_mh);
    cudaGetSymbolAddress((void**)&wqkvh, g_wqkvh);
    cudaGetSymbolAddress((void**)&wprojh,g_wprojh);
    cudaGetSymbolAddress((void**)&wm1h,  g_wm1h);
    cudaGetSymbolAddress((void**)&wm2h,  g_wm2h);
    cudaGetSymbolAddress((void**)&x1,    g_x1);
    cudaGetSymbolAddress((void**)&sqkv,  g_sqkvf);
    cudaGetSymbolAddress((void**)&bqkv,  g_bqkvf);

    // 0) fp16 prep (x, weights, fused qkv scale/bias, mh pad zeros)
    prep_kernel<<<4096, 256>>>(x, w_qk, w_v, w_proj, w_m1, w_m2,
                               s_qk, b_qk, s_v, b_v);
    // 1) fused qkv GEMM: M=768, fp16 out only
    gemm_kernel<<<dim3(32, 6, BSZ), 256>>>(wqkvh, xh, nullptr, sqkv, bqkv,
        nullptr, qkvh, 768, 256, (long)C_BSTRIDE, 0, (long)QKV_BSTRIDE, 0, 0);
    // 2) attention -> g_atth
    attn_kernel<<<dim3(NA / 128, BA * HEADS), 256>>>();
    // 3) dwconv(v) + att add -> g_aph
    dwconv_kernel<<<dim3(16, BSZ * CC), 256>>>(w_pe, s_pe, b_pe);
    // 4) proj: x1 = x + conv1x1(aph, w_proj); fp32 + fp16 outs
    gemm_kernel<<<dim3(32, 2, BSZ), 256>>>(wprojh, aph, x, s_proj, b_proj,
        x1, x1h, 256, 256, (long)C_BSTRIDE, (long)C_BSTRIDE, (long)C_BSTRIDE,
        (long)C_BSTRIDE, 0);
    // 5) m = silu(conv1x1(x1h, w_m1)) -> g_mh (fp16)
    gemm_kernel<<<dim3(32, 3, BSZ), 256>>>(wm1h, x1h, nullptr, s_m1, b_m1,
        nullptr, mh, MLPD, 256, (long)C_BSTRIDE, 0, (long)MH_BSTRIDE, 0, 1);
    // 6) out = x1 + conv1x1(mh, w_m2)  (K=320 padded)
    gemm_kernel<<<dim3(32, 2, BSZ), 256>>>(wm2h, mh, x1, s_m2, b_m2,
        out, nullptr, 256, MLPD_PAD, (long)MH_BSTRIDE, (long)C_BSTRIDE, 0,
        (long)C_BSTRIDE, 0);
}

// round 15
// speedup vs baseline: 1.5555x; 1.0730x over previous
#include <cuda_runtime.h>
#include <cuda_fp16.h>
#include <math.h>

// Problem constants
#define BSZ   2
#define CC    256
#define NN    4096
#define HEADS 8
#define HD    32
#define BA    8
#define NA    1024
#define MLPD  307
#define MLPD_PAD 320
#define M1_PAD   384

#define QKV_BSTRIDE (768*NN)
#define C_BSTRIDE   (CC*NN)
#define MH_BSTRIDE  (MLPD_PAD*NN)

// ---------------- scratch ----------------------------------------------------
__device__ float  g_x1  [BSZ*CC*NN];          // fp32 residual for final add
__device__ __half g_xh  [BSZ*CC*NN];
__device__ __half g_qkvh[BSZ*768*NN];
__device__ __half g_atth[BSZ*CC*NN];
__device__ __half g_aph [BSZ*CC*NN];          // att + pe (proj B input)
__device__ __half g_x1h [BSZ*CC*NN];
__device__ __half g_mh  [BSZ*MLPD_PAD*NN];    // pad rows zeroed by prep
__device__ __half g_wqkvh[768*256];
__device__ __half g_wprojh[256*256];
__device__ __half g_wm1h[M1_PAD*256];         // pad rows zeroed
__device__ __half g_wm2h[256*MLPD_PAD];       // pad cols zeroed
__device__ float  g_sqkvf[768];
__device__ float  g_bqkvf[768];

// ---------------- helpers -----------------------------------------------------
__device__ __forceinline__ float ex2(float x) {
    float r;
    asm("ex2.approx.ftz.f32 %0, %1;" : "=f"(r) : "f"(x));
    return r;
}
__device__ __forceinline__ unsigned smem_u32(const void* p) {
    return (unsigned)__cvta_generic_to_shared(p);
}
__device__ __forceinline__ void cpa16(unsigned dst, const __half* src) {
    unsigned long long g = (unsigned long long)__cvta_generic_to_global((const void*)src);
    asm volatile("cp.async.cg.shared.global [%0], [%1], 16;" :: "r"(dst), "l"(g) : "memory");
}
__device__ __forceinline__ void ldsm4(unsigned* r, unsigned addr) {
    asm volatile("ldmatrix.sync.aligned.m8n8.x4.shared.b16 {%0,%1,%2,%3}, [%4];"
        : "=r"(r[0]), "=r"(r[1]), "=r"(r[2]), "=r"(r[3]) : "r"(addr));
}
__device__ __forceinline__ void ldsm4t(unsigned* r, unsigned addr) {
    asm volatile("ldmatrix.sync.aligned.m8n8.x4.trans.shared.b16 {%0,%1,%2,%3}, [%4];"
        : "=r"(r[0]), "=r"(r[1]), "=r"(r[2]), "=r"(r[3]) : "r"(addr));
}
__device__ __forceinline__ void mma16816(float* c, const unsigned* a,
                                         unsigned b0, unsigned b1) {
    asm volatile("mma.sync.aligned.m16n8k16.row.col.f32.f16.f16.f32 "
        "{%0,%1,%2,%3},{%4,%5,%6,%7},{%8,%9},{%0,%1,%2,%3};"
        : "+f"(c[0]), "+f"(c[1]), "+f"(c[2]), "+f"(c[3])
        : "r"(a[0]), "r"(a[1]), "r"(a[2]), "r"(a[3]), "r"(b0), "r"(b1));
}
__device__ __forceinline__ unsigned pkh2(float a, float b) {
    __half2 h = __floats2half2_rn(a, b);
    return *(unsigned*)&h;
}

// ---------------- prep: fp16 conversions + padding ----------------------------
__global__ void prep_kernel(const float* __restrict__ x,
                            const float* __restrict__ w_qk, const float* __restrict__ w_v,
                            const float* __restrict__ w_proj,
                            const float* __restrict__ w_m1, const float* __restrict__ w_m2,
                            const float* __restrict__ s_qk, const float* __restrict__ b_qk,
                            const float* __restrict__ s_v,  const float* __restrict__ b_v)
{
    const int S0 = BSZ*CC*NN;
    const int S1 = 768*256;
    const int S2 = 256*256;
    const int S3 = M1_PAD*256;
    const int S4 = 256*MLPD_PAD;
    const int S5 = BSZ*(MLPD_PAD-MLPD)*NN;
    const int S6 = 768;
    const int TOT = S0+S1+S2+S3+S4+S5+S6+S6;
    for (int i = blockIdx.x*blockDim.x + threadIdx.x; i < TOT; i += gridDim.x*blockDim.x) {
        int idx = i;
        if (idx < S0) { g_xh[idx] = __float2half_rn(x[idx]); continue; }
        idx -= S0;
        if (idx < S1) {
            g_wqkvh[idx] = __float2half_rn(idx < 512*256 ? w_qk[idx] : w_v[idx-512*256]);
            continue;
        }
        idx -= S1;
        if (idx < S2) { g_wprojh[idx] = __float2half_rn(w_proj[idx]); continue; }
        idx -= S2;
        if (idx < S3) {
            const int r = idx >> 8;
            g_wm1h[idx] = __float2half_rn(r < MLPD ? w_m1[idx] : 0.f);
            continue;
        }
        idx -= S3;
        if (idx < S4) {
            const int r = idx / MLPD_PAD, c = idx % MLPD_PAD;
            g_wm2h[idx] = __float2half_rn(c < MLPD ? w_m2[r*MLPD + c] : 0.f);
            continue;
        }
        idx -= S4;
        if (idx < S5) {
            const int b  = idx / ((MLPD_PAD-MLPD)*NN);
            const int rr = idx % ((MLPD_PAD-MLPD)*NN);
            g_mh[(long)b*MH_BSTRIDE + MLPD*NN + rr] = __float2half_rn(0.f);
            continue;
        }
        idx -= S5;
        if (idx < S6) { g_sqkvf[idx] = idx < 512 ? s_qk[idx] : s_v[idx-512]; continue; }
        idx -= S6;
        g_bqkvf[idx] = idx < 512 ? b_qk[idx] : b_v[idx-512];
    }
}

// ---- conv1x1 GEMM via HMMA + cp.async: 128m x 128n, 8 warps (64m x 32n) ------
// (identical to R14 — verified)
#define BKK 32
#define AP  (BKK + 8)
#define BP  (128 + 8)

__global__ __launch_bounds__(256, 2)
void gemm_kernel(const __half* __restrict__ Ag_,
                 const __half* __restrict__ Bg_,
                 const float* __restrict__ res,
                 const float* __restrict__ sc,
                 const float* __restrict__ bi,
                 float* __restrict__ Cf_,
                 __half* __restrict__ Ch_,
                 int M, int K,
                 long sB, long sCf, long sCh, long sR, int epi)
{
    __shared__ __align__(16) __half As[2][128][AP];
    __shared__ __align__(16) __half Bs[2][BKK][BP];

    const int b = blockIdx.z;
    const __half* Ag = Ag_;
    const __half* Bg = Bg_ + (long)b * sB;
    const float*  Rb = res ? (res + (long)b * sR) : nullptr;
    float*  Cf = Cf_ ? (Cf_ + (long)b * sCf) : nullptr;
    __half* Ch = Ch_ ? (Ch_ + (long)b * sCh) : nullptr;

    const int m0 = blockIdx.y * 128;
    const int n0 = blockIdx.x * 128;
    const int tid  = threadIdx.x;
    const int lane = tid & 31;
    const int wid  = tid >> 5;
    const int wm = (wid >> 2) * 64;
    const int wn = (wid & 3) * 32;

    const int nkt = K / BKK;

    float acc[4][4][4] = {};

    #define ISSUE(KT)                                                          \
    {                                                                          \
        const int k0 = (KT) * BKK;                                             \
        const int st = (KT) & 1;                                               \
        const __half* ap = Ag + (long)(m0 + (tid >> 1)) * K + k0 + (tid & 1) * 16; \
        cpa16(smem_u32(&As[st][tid >> 1][(tid & 1) * 16]), ap);                \
        cpa16(smem_u32(&As[st][tid >> 1][(tid & 1) * 16 + 8]), ap + 8);        \
        const __half* bp = Bg + (long)(k0 + (tid >> 3)) * NN + n0 + (tid & 7) * 16; \
        cpa16(smem_u32(&Bs[st][tid >> 3][(tid & 7) * 16]), bp);                \
        cpa16(smem_u32(&Bs[st][tid >> 3][(tid & 7) * 16 + 8]), bp + 8);        \
        asm volatile("cp.async.commit_group;" ::: "memory");                   \
    }

    ISSUE(0)

    for (int kt = 0; kt < nkt; kt++) {
        if (kt + 1 < nkt) {
            ISSUE(kt + 1)
            asm volatile("cp.async.wait_group 1;" ::: "memory");
        } else {
            asm volatile("cp.async.wait_group 0;" ::: "memory");
        }
        __syncthreads();
        const int buf = kt & 1;
        #pragma unroll
        for (int ks = 0; ks < BKK; ks += 16) {
            unsigned afr[4][4], bfr[2][4];
            #pragma unroll
            for (int mi = 0; mi < 4; mi++) {
                const unsigned addr = smem_u32(
                    &As[buf][wm + mi * 16 + (lane & 15)][ks + (lane >> 4) * 8]);
                ldsm4(afr[mi], addr);
            }
            #pragma unroll
            for (int g = 0; g < 2; g++) {
                const int row = ks + (lane & 15);
                const int col = wn + g * 16 + ((lane >> 4) * 8);
                ldsm4t(bfr[g], smem_u32(&Bs[buf][row][col]));
            }
            #pragma unroll
            for (int mi = 0; mi < 4; mi++)
                #pragma unroll
                for (int g = 0; g < 2; g++) {
                    mma16816(acc[mi][2 * g],     afr[mi], bfr[g][0], bfr[g][1]);
                    mma16816(acc[mi][2 * g + 1], afr[mi], bfr[g][2], bfr[g][3]);
                }
        }
        __syncthreads();
    }
    #undef ISSUE

    #pragma unroll
    for (int mi = 0; mi < 4; mi++) {
        #pragma unroll
        for (int hh = 0; hh < 2; hh++) {
            const int m = m0 + wm + mi * 16 + (lane >> 2) + hh * 8;
            if (m >= M) continue;
            const float scl = sc[m], bia = bi[m];
            #pragma unroll
            for (int ni = 0; ni < 4; ni++) {
                float v0 = acc[mi][ni][2 * hh]     * scl + bia;
                float v1 = acc[mi][ni][2 * hh + 1] * scl + bia;
                if (epi == 1) {
                    v0 = v0 / (1.f + __expf(-v0));
                    v1 = v1 / (1.f + __expf(-v1));
                }
                const int n = n0 + wn + ni * 8 + (lane & 3) * 2;
                const long base = (long)m * NN + n;
                if (Rb) {
                    const float2 r = *(const float2*)(Rb + base);
                    v0 += r.x; v1 += r.y;
                }
                if (Cf) *(float2*)(Cf + base) = make_float2(v0, v1);
                if (Ch) *(__half2*)(Ch + base) = __floats2half2_rn(v0, v1);
            }
        }
    }
}

// ---- depthwise 3x3, smem-tiled: one CTA per (b,c) plane -----------------------
// out = sum(v * (w_pe*s[c])) + bi[c] + att   -> g_aph (fp16)
__global__ __launch_bounds__(256)
void dwconv_kernel(const float* __restrict__ w_pe,
                   const float* __restrict__ s,
                   const float* __restrict__ bi)
{
    __shared__ __align__(16) __half plane[4096];

    const int bc = blockIdx.x;
    const int b = bc >> 8, c = bc & 255;
    const int tid = threadIdx.x;

    const __half* src = g_qkvh + (long)b * QKV_BSTRIDE + (long)(512 + c) * NN;

    // coalesced plane load: 16 halves (2x uint4) per thread
    {
        const int o = tid * 16;
        *(uint4*)&plane[o]     = *(const uint4*)(src + o);
        *(uint4*)&plane[o + 8] = *(const uint4*)(src + o + 8);
    }

    // weights folded with scale (uniform across block -> const-cached)
    const float sc = s[c];
    float wk[9];
    #pragma unroll
    for (int j = 0; j < 9; j++) wk[j] = w_pe[c * 9 + j] * sc;
    const float bia = bi[c];

    __syncthreads();

    // each thread: 16 contiguous pixels of row h
    const int h  = tid >> 2;
    const int w0 = (tid & 3) * 16;

    float r[3][18];
    #pragma unroll
    for (int rr = 0; rr < 3; rr++) {
        const int row = h + rr - 1;
        if (row < 0 || row >= 64) {
            #pragma unroll
            for (int j = 0; j < 18; j++) r[rr][j] = 0.f;
        } else {
            const __half* p = &plane[row * 64];
            #pragma unroll
            for (int j = 0; j < 18; j++) {
                const int col = w0 - 1 + j;
                r[rr][j] = (col >= 0 && col < 64) ? __half2float(p[col]) : 0.f;
            }
        }
    }

    const long o = (long)b * C_BSTRIDE + (long)c * NN + h * 64 + w0;
    uint4 a0 = *(const uint4*)(g_atth + o);
    uint4 a1 = *(const uint4*)(g_atth + o + 8);
    const __half2* ah0 = (const __half2*)&a0;
    const __half2* ah1 = (const __half2*)&a1;

    uint4 o0, o1;
    __half2* oh0 = (__half2*)&o0;
    __half2* oh1 = (__half2*)&o1;

    #pragma unroll
    for (int i = 0; i < 16; i++) {
        float acc = bia;
        #pragma unroll
        for (int rr = 0; rr < 3; rr++) {
            acc = fmaf(r[rr][i],     wk[rr * 3 + 0], acc);
            acc = fmaf(r[rr][i + 1], wk[rr * 3 + 1], acc);
            acc = fmaf(r[rr][i + 2], wk[rr * 3 + 2], acc);
        }
        const float2 av = (i < 8) ? __half22float2(ah0[i >> 1])
                                  : __half22float2(ah1[(i - 8) >> 1]);
        const float att = (i & 1) ? av.y : av.x;
        const float v = acc + att;
        __half hv = __float2half_rn(v);
        if (i < 8) {
            ((__half*)oh0)[i] = hv;
        } else {
            ((__half*)oh1)[i - 8] = hv;
        }
    }
    *(uint4*)(g_aph + o)     = o0;
    *(uint4*)(g_aph + o + 8) = o1;
}

// ---- area attention via HMMA (identical to R14 — verified) --------------------
#define PITCH 136

__global__ __launch_bounds__(256)
void attn_kernel()
{
    __shared__ __align__(16) __half Qs[32][PITCH];
    __shared__ __align__(16) __half Ks[32][PITCH];
    __shared__ __align__(16) __half Vs[32][PITCH];

    const int ba = blockIdx.y >> 3;
    const int h  = blockIdx.y & 7;
    const int q0 = blockIdx.x * 128;
    const int tid  = threadIdx.x;
    const int lane = tid & 31;
    const int wid  = tid >> 5;
    const int wq   = wid * 16;

    const float scale = 0.17677669529663687f * 1.4426950408889634f;

    const long qflat0 = (long)ba * 524288 + (long)(h * HD) * 1024;
    const long kflat0 = qflat0 + 256 * 1024;
    const long vflat0 = (long)ba * 262144 + (long)(h * HD) * 1024;

    const int fd = tid >> 3;
    const int fg = (tid & 7) * 16;

    {
        const long f = qflat0 + (long)fd * 1024 + q0 + fg;
        const __half* src = &g_qkvh[(f >> 21) * QKV_BSTRIDE + (f & 2097151)];
        uint4 u0 = *(const uint4*)src;
        uint4 u1 = *(const uint4*)(src + 8);
        __half2* p0 = (__half2*)&u0;
        __half2* p1 = (__half2*)&u1;
        #pragma unroll
        for (int j = 0; j < 4; j++) {
            float2 f0 = __half22float2(p0[j]);
            p0[j] = __floats2half2_rn(f0.x * scale, f0.y * scale);
            float2 f1 = __half22float2(p1[j]);
            p1[j] = __floats2half2_rn(f1.x * scale, f1.y * scale);
        }
        *(uint4*)&Qs[fd][fg]     = u0;
        *(uint4*)&Qs[fd][fg + 8] = u1;
    }
    __syncthreads();

    unsigned aq[2][4];
    #pragma unroll
    for (int dc = 0; dc < 2; dc++) {
        const int row = dc * 16 + (lane & 7) + ((lane >> 4) & 1) * 8;
        const int col = wq + ((lane >> 3) & 1) * 8;
        ldsm4t(aq[dc], smem_u32(&Qs[row][col]));
    }

    float oacc[4][4] = {};
    float lsum0 = 0.f, lsum1 = 0.f;

    for (int m0 = 0; m0 < NA; m0 += 128) {
        __syncthreads();
        {
            const long fk = kflat0 + (long)fd * 1024 + m0 + fg;
            const __half* sk = &g_qkvh[(fk >> 21) * QKV_BSTRIDE + (fk & 2097151)];
            *(uint4*)&Ks[fd][fg]     = *(const uint4*)sk;
            *(uint4*)&Ks[fd][fg + 8] = *(const uint4*)(sk + 8);
            const long fv = vflat0 + (long)fd * 1024 + m0 + fg;
            const __half* sv = &g_qkvh[(fv >> 20) * QKV_BSTRIDE + 512 * NN + (fv & 1048575)];
            *(uint4*)&Vs[fd][fg]     = *(const uint4*)sv;
            *(uint4*)&Vs[fd][fg + 8] = *(const uint4*)(sv + 8);
        }
        __syncthreads();

        float sacc[16][4];
        #pragma unroll
        for (int nt = 0; nt < 16; nt++) {
            sacc[nt][0] = 0.f; sacc[nt][1] = 0.f;
            sacc[nt][2] = 0.f; sacc[nt][3] = 0.f;
        }
        #pragma unroll
        for (int dc = 0; dc < 2; dc++) {
            #pragma unroll
            for (int ntp = 0; ntp < 8; ntp++) {
                unsigned bk[4];
                const int row = dc * 16 + (lane & 7) + ((lane >> 3) & 1) * 8;
                const int col = ntp * 16 + ((lane >> 4) & 1) * 8;
                ldsm4t(bk, smem_u32(&Ks[row][col]));
                mma16816(sacc[2 * ntp],     aq[dc], bk[0], bk[1]);
                mma16816(sacc[2 * ntp + 1], aq[dc], bk[2], bk[3]);
            }
        }
        #pragma unroll
        for (int nt = 0; nt < 16; nt++) {
            sacc[nt][0] = ex2(sacc[nt][0]);
            sacc[nt][1] = ex2(sacc[nt][1]);
            sacc[nt][2] = ex2(sacc[nt][2]);
            sacc[nt][3] = ex2(sacc[nt][3]);
            lsum0 += sacc[nt][0] + sacc[nt][1];
            lsum1 += sacc[nt][2] + sacc[nt][3];
        }
        #pragma unroll
        for (int kt = 0; kt < 8; kt++) {
            unsigned pa[4];
            pa[0] = pkh2(sacc[2 * kt][0],     sacc[2 * kt][1]);
            pa[1] = pkh2(sacc[2 * kt][2],     sacc[2 * kt][3]);
            pa[2] = pkh2(sacc[2 * kt + 1][0], sacc[2 * kt + 1][1]);
            pa[3] = pkh2(sacc[2 * kt + 1][2], sacc[2 * kt + 1][3]);
            #pragma unroll
            for (int dtp = 0; dtp < 2; dtp++) {
                unsigned bv[4];
                const int row = dtp * 16 + (lane & 7) + ((lane >> 4) & 1) * 8;
                const int col = kt * 16 + ((lane >> 3) & 1) * 8;
                ldsm4(bv, smem_u32(&Vs[row][col]));
                mma16816(oacc[2 * dtp],     pa, bv[0], bv[1]);
                mma16816(oacc[2 * dtp + 1], pa, bv[2], bv[3]);
            }
        }
    }

    lsum0 += __shfl_xor_sync(0xffffffff, lsum0, 1);
    lsum0 += __shfl_xor_sync(0xffffffff, lsum0, 2);
    lsum1 += __shfl_xor_sync(0xffffffff, lsum1, 1);
    lsum1 += __shfl_xor_sync(0xffffffff, lsum1, 2);
    const float inv0 = 1.f / lsum0;
    const float inv1 = 1.f / lsum1;

    const int qg = q0 + wq + (lane >> 2);
    #pragma unroll
    for (int dt = 0; dt < 4; dt++) {
        const int d = dt * 8 + (lane & 3) * 2;
        #pragma unroll
        for (int e = 0; e < 2; e++) {
            const long f0 = vflat0 + (long)(d + e) * 1024 + qg;
            g_atth[(f0 >> 20) * C_BSTRIDE + (f0 & 1048575)] =
                __float2half_rn(oacc[dt][e] * inv0);
            const long f1 = f0 + 8;
            g_atth[(f1 >> 20) * C_BSTRIDE + (f1 & 1048575)] =
                __float2half_rn(oacc[dt][2 + e] * inv1);
        }
    }
}

// ---------------- launch -------------------------------------------------------
extern "C" void kernel_launch(void* const* d_in, const int* in_sizes, int n_in,
                              void* d_out, int out_size)
{
    const float* x      = (const float*)d_in[0];
    const float* w_qk   = (const float*)d_in[1];
    const float* s_qk   = (const float*)d_in[2];
    const float* b_qk   = (const float*)d_in[3];
    const float* w_v    = (const float*)d_in[4];
    const float* s_v    = (const float*)d_in[5];
    const float* b_v    = (const float*)d_in[6];
    const float* w_pe   = (const float*)d_in[7];
    const float* s_pe   = (const float*)d_in[8];
    const float* b_pe   = (const float*)d_in[9];
    const float* w_proj = (const float*)d_in[10];
    const float* s_proj = (const float*)d_in[11];
    const float* b_proj = (const float*)d_in[12];
    const float* w_m1   = (const float*)d_in[13];
    const float* s_m1   = (const float*)d_in[14];
    const float* b_m1   = (const float*)d_in[15];
    const float* w_m2   = (const float*)d_in[16];
    const float* s_m2   = (const float*)d_in[17];
    const float* b_m2   = (const float*)d_in[18];
    float* out = (float*)d_out;

    __half *xh, *qkvh, *aph, *x1h, *mh, *wqkvh, *wprojh, *wm1h, *wm2h;
    float *x1, *sqkv, *bqkv;
    cudaGetSymbolAddress((void**)&xh,    g_xh);
    cudaGetSymbolAddress((void**)&qkvh,  g_qkvh);
    cudaGetSymbolAddress((void**)&aph,   g_aph);
    cudaGetSymbolAddress((void**)&x1h,   g_x1h);
    cudaGetSymbolAddress((void**)&mh,    g_mh);
    cudaGetSymbolAddress((void**)&wqkvh, g_wqkvh);
    cudaGetSymbolAddress((void**)&wprojh,g_wprojh);
    cudaGetSymbolAddress((void**)&wm1h,  g_wm1h);
    cudaGetSymbolAddress((void**)&wm2h,  g_wm2h);
    cudaGetSymbolAddress((void**)&x1,    g_x1);
    cudaGetSymbolAddress((void**)&sqkv,  g_sqkvf);
    cudaGetSymbolAddress((void**)&bqkv,  g_bqkvf);

    // 0) fp16 prep
    prep_kernel<<<4096, 256>>>(x, w_qk, w_v, w_proj, w_m1, w_m2,
                               s_qk, b_qk, s_v, b_v);
    // 1) fused qkv GEMM: M=768, fp16 out
    gemm_kernel<<<dim3(32, 6, BSZ), 256>>>(wqkvh, xh, nullptr, sqkv, bqkv,
        nullptr, qkvh, 768, 256, (long)C_BSTRIDE, 0, (long)QKV_BSTRIDE, 0, 0);
    // 2) attention -> g_atth
    attn_kernel<<<dim3(NA / 128, BA * HEADS), 256>>>();
    // 3) dwconv(v) + att add -> g_aph (smem-tiled)
    dwconv_kernel<<<BSZ * CC, 256>>>(w_pe, s_pe, b_pe);
    // 4) proj: x1 = x + conv1x1(aph, w_proj)
    gemm_kernel<<<dim3(32, 2, BSZ), 256>>>(wprojh, aph, x, s_proj, b_proj,
        x1, x1h, 256, 256, (long)C_BSTRIDE, (long)C_BSTRIDE, (long)C_BSTRIDE,
        (long)C_BSTRIDE, 0);
    // 5) m = silu(conv1x1(x1h, w_m1))
    gemm_kernel<<<dim3(32, 3, BSZ), 256>>>(wm1h, x1h, nullptr, s_m1, b_m1,
        nullptr, mh, MLPD, 256, (long)C_BSTRIDE, 0, (long)MH_BSTRIDE, 0, 1);
    // 6) out = x1 + conv1x1(mh, w_m2)  (K=320 padded)
    gemm_kernel<<<dim3(32, 2, BSZ), 256>>>(wm2h, mh, x1, s_m2, b_m2,
        out, nullptr, 256, MLPD_PAD, (long)MH_BSTRIDE, (long)C_BSTRIDE, 0,
        (long)C_BSTRIDE, 0);
}

// round 16
// speedup vs baseline: 1.6174x; 1.0398x over previous
#include <cuda_runtime.h>
#include <cuda_fp16.h>
#include <math.h>

// Problem constants
#define BSZ   2
#define CC    256
#define NN    4096
#define HEADS 8
#define HD    32
#define BA    8
#define NA    1024
#define MLPD  307
#define MLPD_PAD 320
#define M1_PAD   384

#define QKV_BSTRIDE (768*NN)
#define C_BSTRIDE   (CC*NN)
#define MH_BSTRIDE  (MLPD_PAD*NN)

// ---------------- scratch ----------------------------------------------------
__device__ float  g_x1  [BSZ*CC*NN];
__device__ __half g_xh  [BSZ*CC*NN];
__device__ __half g_qkvh[BSZ*768*NN];
__device__ __half g_atth[BSZ*CC*NN];
__device__ __half g_aph [BSZ*CC*NN];
__device__ __half g_x1h [BSZ*CC*NN];
__device__ __half g_mh  [BSZ*MLPD_PAD*NN];
__device__ __half g_wqkvh[768*256];
__device__ __half g_wprojh[256*256];
__device__ __half g_wm1h[M1_PAD*256];
__device__ __half g_wm2h[256*MLPD_PAD];
__device__ float  g_sqkvf[768];
__device__ float  g_bqkvf[768];

// ---------------- helpers -----------------------------------------------------
__device__ __forceinline__ float ex2(float x) {
    float r;
    asm("ex2.approx.ftz.f32 %0, %1;" : "=f"(r) : "f"(x));
    return r;
}
__device__ __forceinline__ unsigned smem_u32(const void* p) {
    return (unsigned)__cvta_generic_to_shared(p);
}
__device__ __forceinline__ void cpa16(unsigned dst, const __half* src) {
    unsigned long long g = (unsigned long long)__cvta_generic_to_global((const void*)src);
    asm volatile("cp.async.cg.shared.global [%0], [%1], 16;" :: "r"(dst), "l"(g) : "memory");
}
__device__ __forceinline__ void ldsm4(unsigned* r, unsigned addr) {
    asm volatile("ldmatrix.sync.aligned.m8n8.x4.shared.b16 {%0,%1,%2,%3}, [%4];"
        : "=r"(r[0]), "=r"(r[1]), "=r"(r[2]), "=r"(r[3]) : "r"(addr));
}
__device__ __forceinline__ void ldsm4t(unsigned* r, unsigned addr) {
    asm volatile("ldmatrix.sync.aligned.m8n8.x4.trans.shared.b16 {%0,%1,%2,%3}, [%4];"
        : "=r"(r[0]), "=r"(r[1]), "=r"(r[2]), "=r"(r[3]) : "r"(addr));
}
__device__ __forceinline__ void mma16816(float* c, const unsigned* a,
                                         unsigned b0, unsigned b1) {
    asm volatile("mma.sync.aligned.m16n8k16.row.col.f32.f16.f16.f32 "
        "{%0,%1,%2,%3},{%4,%5,%6,%7},{%8,%9},{%0,%1,%2,%3};"
        : "+f"(c[0]), "+f"(c[1]), "+f"(c[2]), "+f"(c[3])
        : "r"(a[0]), "r"(a[1]), "r"(a[2]), "r"(a[3]), "r"(b0), "r"(b1));
}
__device__ __forceinline__ unsigned pkh2(float a, float b) {
    __half2 h = __floats2half2_rn(a, b);
    return *(unsigned*)&h;
}

// ---------------- prep: fp16 conversions + padding ----------------------------
__global__ void prep_kernel(const float* __restrict__ x,
                            const float* __restrict__ w_qk, const float* __restrict__ w_v,
                            const float* __restrict__ w_proj,
                            const float* __restrict__ w_m1, const float* __restrict__ w_m2,
                            const float* __restrict__ s_qk, const float* __restrict__ b_qk,
                            const float* __restrict__ s_v,  const float* __restrict__ b_v)
{
    const int S0 = BSZ*CC*NN;
    const int S1 = 768*256;
    const int S2 = 256*256;
    const int S3 = M1_PAD*256;
    const int S4 = 256*MLPD_PAD;
    const int S5 = BSZ*(MLPD_PAD-MLPD)*NN;
    const int S6 = 768;
    const int TOT = S0+S1+S2+S3+S4+S5+S6+S6;
    for (int i = blockIdx.x*blockDim.x + threadIdx.x; i < TOT; i += gridDim.x*blockDim.x) {
        int idx = i;
        if (idx < S0) { g_xh[idx] = __float2half_rn(x[idx]); continue; }
        idx -= S0;
        if (idx < S1) {
            g_wqkvh[idx] = __float2half_rn(idx < 512*256 ? w_qk[idx] : w_v[idx-512*256]);
            continue;
        }
        idx -= S1;
        if (idx < S2) { g_wprojh[idx] = __float2half_rn(w_proj[idx]); continue; }
        idx -= S2;
        if (idx < S3) {
            const int r = idx >> 8;
            g_wm1h[idx] = __float2half_rn(r < MLPD ? w_m1[idx] : 0.f);
            continue;
        }
        idx -= S3;
        if (idx < S4) {
            const int r = idx / MLPD_PAD, c = idx % MLPD_PAD;
            g_wm2h[idx] = __float2half_rn(c < MLPD ? w_m2[r*MLPD + c] : 0.f);
            continue;
        }
        idx -= S4;
        if (idx < S5) {
            const int b  = idx / ((MLPD_PAD-MLPD)*NN);
            const int rr = idx % ((MLPD_PAD-MLPD)*NN);
            g_mh[(long)b*MH_BSTRIDE + MLPD*NN + rr] = __float2half_rn(0.f);
            continue;
        }
        idx -= S5;
        if (idx < S6) { g_sqkvf[idx] = idx < 512 ? s_qk[idx] : s_v[idx-512]; continue; }
        idx -= S6;
        g_bqkvf[idx] = idx < 512 ? b_qk[idx] : b_v[idx-512];
    }
}

// ---- conv1x1 GEMM via HMMA + cp.async (identical to R14 — verified) ----------
#define BKK 32
#define AP  (BKK + 8)
#define BP  (128 + 8)

__global__ __launch_bounds__(256, 2)
void gemm_kernel(const __half* __restrict__ Ag_,
                 const __half* __restrict__ Bg_,
                 const float* __restrict__ res,
                 const float* __restrict__ sc,
                 const float* __restrict__ bi,
                 float* __restrict__ Cf_,
                 __half* __restrict__ Ch_,
                 int M, int K,
                 long sB, long sCf, long sCh, long sR, int epi)
{
    __shared__ __align__(16) __half As[2][128][AP];
    __shared__ __align__(16) __half Bs[2][BKK][BP];

    const int b = blockIdx.z;
    const __half* Ag = Ag_;
    const __half* Bg = Bg_ + (long)b * sB;
    const float*  Rb = res ? (res + (long)b * sR) : nullptr;
    float*  Cf = Cf_ ? (Cf_ + (long)b * sCf) : nullptr;
    __half* Ch = Ch_ ? (Ch_ + (long)b * sCh) : nullptr;

    const int m0 = blockIdx.y * 128;
    const int n0 = blockIdx.x * 128;
    const int tid  = threadIdx.x;
    const int lane = tid & 31;
    const int wid  = tid >> 5;
    const int wm = (wid >> 2) * 64;
    const int wn = (wid & 3) * 32;

    const int nkt = K / BKK;

    float acc[4][4][4] = {};

    #define ISSUE(KT)                                                          \
    {                                                                          \
        const int k0 = (KT) * BKK;                                             \
        const int st = (KT) & 1;                                               \
        const __half* ap = Ag + (long)(m0 + (tid >> 1)) * K + k0 + (tid & 1) * 16; \
        cpa16(smem_u32(&As[st][tid >> 1][(tid & 1) * 16]), ap);                \
        cpa16(smem_u32(&As[st][tid >> 1][(tid & 1) * 16 + 8]), ap + 8);        \
        const __half* bp = Bg + (long)(k0 + (tid >> 3)) * NN + n0 + (tid & 7) * 16; \
        cpa16(smem_u32(&Bs[st][tid >> 3][(tid & 7) * 16]), bp);                \
        cpa16(smem_u32(&Bs[st][tid >> 3][(tid & 7) * 16 + 8]), bp + 8);        \
        asm volatile("cp.async.commit_group;" ::: "memory");                   \
    }

    ISSUE(0)

    for (int kt = 0; kt < nkt; kt++) {
        if (kt + 1 < nkt) {
            ISSUE(kt + 1)
            asm volatile("cp.async.wait_group 1;" ::: "memory");
        } else {
            asm volatile("cp.async.wait_group 0;" ::: "memory");
        }
        __syncthreads();
        const int buf = kt & 1;
        #pragma unroll
        for (int ks = 0; ks < BKK; ks += 16) {
            unsigned afr[4][4], bfr[2][4];
            #pragma unroll
            for (int mi = 0; mi < 4; mi++) {
                const unsigned addr = smem_u32(
                    &As[buf][wm + mi * 16 + (lane & 15)][ks + (lane >> 4) * 8]);
                ldsm4(afr[mi], addr);
            }
            #pragma unroll
            for (int g = 0; g < 2; g++) {
                const int row = ks + (lane & 15);
                const int col = wn + g * 16 + ((lane >> 4) * 8);
                ldsm4t(bfr[g], smem_u32(&Bs[buf][row][col]));
            }
            #pragma unroll
            for (int mi = 0; mi < 4; mi++)
                #pragma unroll
                for (int g = 0; g < 2; g++) {
                    mma16816(acc[mi][2 * g],     afr[mi], bfr[g][0], bfr[g][1]);
                    mma16816(acc[mi][2 * g + 1], afr[mi], bfr[g][2], bfr[g][3]);
                }
        }
        __syncthreads();
    }
    #undef ISSUE

    #pragma unroll
    for (int mi = 0; mi < 4; mi++) {
        #pragma unroll
        for (int hh = 0; hh < 2; hh++) {
            const int m = m0 + wm + mi * 16 + (lane >> 2) + hh * 8;
            if (m >= M) continue;
            const float scl = sc[m], bia = bi[m];
            #pragma unroll
            for (int ni = 0; ni < 4; ni++) {
                float v0 = acc[mi][ni][2 * hh]     * scl + bia;
                float v1 = acc[mi][ni][2 * hh + 1] * scl + bia;
                if (epi == 1) {
                    v0 = v0 / (1.f + __expf(-v0));
                    v1 = v1 / (1.f + __expf(-v1));
                }
                const int n = n0 + wn + ni * 8 + (lane & 3) * 2;
                const long base = (long)m * NN + n;
                if (Rb) {
                    const float2 r = *(const float2*)(Rb + base);
                    v0 += r.x; v1 += r.y;
                }
                if (Cf) *(float2*)(Cf + base) = make_float2(v0, v1);
                if (Ch) *(__half2*)(Ch + base) = __floats2half2_rn(v0, v1);
            }
        }
    }
}

// ---- depthwise 3x3, smem-tiled (identical to R15 — verified 7.7us) -----------
__global__ __launch_bounds__(256)
void dwconv_kernel(const float* __restrict__ w_pe,
                   const float* __restrict__ s,
                   const float* __restrict__ bi)
{
    __shared__ __align__(16) __half plane[4096];

    const int bc = blockIdx.x;
    const int b = bc >> 8, c = bc & 255;
    const int tid = threadIdx.x;

    const __half* src = g_qkvh + (long)b * QKV_BSTRIDE + (long)(512 + c) * NN;
    {
        const int o = tid * 16;
        *(uint4*)&plane[o]     = *(const uint4*)(src + o);
        *(uint4*)&plane[o + 8] = *(const uint4*)(src + o + 8);
    }

    const float sc = s[c];
    float wk[9];
    #pragma unroll
    for (int j = 0; j < 9; j++) wk[j] = w_pe[c * 9 + j] * sc;
    const float bia = bi[c];

    __syncthreads();

    const int h  = tid >> 2;
    const int w0 = (tid & 3) * 16;

    float r[3][18];
    #pragma unroll
    for (int rr = 0; rr < 3; rr++) {
        const int row = h + rr - 1;
        if (row < 0 || row >= 64) {
            #pragma unroll
            for (int j = 0; j < 18; j++) r[rr][j] = 0.f;
        } else {
            const __half* p = &plane[row * 64];
            #pragma unroll
            for (int j = 0; j < 18; j++) {
                const int col = w0 - 1 + j;
                r[rr][j] = (col >= 0 && col < 64) ? __half2float(p[col]) : 0.f;
            }
        }
    }

    const long o = (long)b * C_BSTRIDE + (long)c * NN + h * 64 + w0;
    uint4 a0 = *(const uint4*)(g_atth + o);
    uint4 a1 = *(const uint4*)(g_atth + o + 8);
    const __half2* ah0 = (const __half2*)&a0;
    const __half2* ah1 = (const __half2*)&a1;

    uint4 o0, o1;
    __half2* oh0 = (__half2*)&o0;
    __half2* oh1 = (__half2*)&o1;

    #pragma unroll
    for (int i = 0; i < 16; i++) {
        float acc = bia;
        #pragma unroll
        for (int rr = 0; rr < 3; rr++) {
            acc = fmaf(r[rr][i],     wk[rr * 3 + 0], acc);
            acc = fmaf(r[rr][i + 1], wk[rr * 3 + 1], acc);
            acc = fmaf(r[rr][i + 2], wk[rr * 3 + 2], acc);
        }
        const float2 av = (i < 8) ? __half22float2(ah0[i >> 1])
                                  : __half22float2(ah1[(i - 8) >> 1]);
        const float att = (i & 1) ? av.y : av.x;
        __half hv = __float2half_rn(acc + att);
        if (i < 8) ((__half*)oh0)[i] = hv;
        else       ((__half*)oh1)[i - 8] = hv;
    }
    *(uint4*)(g_aph + o)     = o0;
    *(uint4*)(g_aph + o + 8) = o1;
}

// ---- area attention via HMMA, cp.async double-buffered K/V -------------------
#define PITCH 136

__global__ __launch_bounds__(256)
void attn_kernel()
{
    __shared__ __align__(16) __half Qs[32][PITCH];
    __shared__ __align__(16) __half Ks[2][32][PITCH];
    __shared__ __align__(16) __half Vs[2][32][PITCH];

    const int ba = blockIdx.y >> 3;
    const int h  = blockIdx.y & 7;
    const int q0 = blockIdx.x * 128;
    const int tid  = threadIdx.x;
    const int lane = tid & 31;
    const int wid  = tid >> 5;
    const int wq   = wid * 16;

    const float scale = 0.17677669529663687f * 1.4426950408889634f;

    const long qflat0 = (long)ba * 524288 + (long)(h * HD) * 1024;
    const long kflat0 = qflat0 + 256 * 1024;
    const long vflat0 = (long)ba * 262144 + (long)(h * HD) * 1024;

    const int fd = tid >> 3;
    const int fg = (tid & 7) * 16;

    // per-thread global source pointers for K/V tile fills (advance by chunk)
    const long fk0 = kflat0 + (long)fd * 1024 + fg;
    const __half* kp = &g_qkvh[(fk0 >> 21) * QKV_BSTRIDE + (fk0 & 2097151)];
    const long fv0 = vflat0 + (long)fd * 1024 + fg;
    const __half* vp = &g_qkvh[(fv0 >> 20) * QKV_BSTRIDE + 512 * NN + (fv0 & 1048575)];

    #define ISSUE_KV(CH)                                                       \
    {                                                                          \
        const int st = (CH) & 1;                                               \
        const int off = (CH) * 128;                                            \
        cpa16(smem_u32(&Ks[st][fd][fg]),     kp + off);                        \
        cpa16(smem_u32(&Ks[st][fd][fg + 8]), kp + off + 8);                    \
        cpa16(smem_u32(&Vs[st][fd][fg]),     vp + off);                        \
        cpa16(smem_u32(&Vs[st][fd][fg + 8]), vp + off + 8);                    \
        asm volatile("cp.async.commit_group;" ::: "memory");                   \
    }

    ISSUE_KV(0)

    // Q fill (once, scaled)
    {
        const long f = qflat0 + (long)fd * 1024 + q0 + fg;
        const __half* src = &g_qkvh[(f >> 21) * QKV_BSTRIDE + (f & 2097151)];
        uint4 u0 = *(const uint4*)src;
        uint4 u1 = *(const uint4*)(src + 8);
        __half2* p0 = (__half2*)&u0;
        __half2* p1 = (__half2*)&u1;
        #pragma unroll
        for (int j = 0; j < 4; j++) {
            float2 f0 = __half22float2(p0[j]);
            p0[j] = __floats2half2_rn(f0.x * scale, f0.y * scale);
            float2 f1 = __half22float2(p1[j]);
            p1[j] = __floats2half2_rn(f1.x * scale, f1.y * scale);
        }
        *(uint4*)&Qs[fd][fg]     = u0;
        *(uint4*)&Qs[fd][fg + 8] = u1;
    }
    __syncthreads();

    unsigned aq[2][4];
    #pragma unroll
    for (int dc = 0; dc < 2; dc++) {
        const int row = dc * 16 + (lane & 7) + ((lane >> 4) & 1) * 8;
        const int col = wq + ((lane >> 3) & 1) * 8;
        ldsm4t(aq[dc], smem_u32(&Qs[row][col]));
    }

    float oacc[4][4] = {};
    float lsum0 = 0.f, lsum1 = 0.f;

    for (int ch = 0; ch < 8; ch++) {
        asm volatile("cp.async.wait_group 0;" ::: "memory");
        __syncthreads();                       // copy visible to all
        if (ch + 1 < 8) ISSUE_KV(ch + 1)       // overlaps with compute below
        const int buf = ch & 1;

        float sacc[16][4];
        #pragma unroll
        for (int nt = 0; nt < 16; nt++) {
            sacc[nt][0] = 0.f; sacc[nt][1] = 0.f;
            sacc[nt][2] = 0.f; sacc[nt][3] = 0.f;
        }
        #pragma unroll
        for (int dc = 0; dc < 2; dc++) {
            #pragma unroll
            for (int ntp = 0; ntp < 8; ntp++) {
                unsigned bk[4];
                const int row = dc * 16 + (lane & 7) + ((lane >> 3) & 1) * 8;
                const int col = ntp * 16 + ((lane >> 4) & 1) * 8;
                ldsm4t(bk, smem_u32(&Ks[buf][row][col]));
                mma16816(sacc[2 * ntp],     aq[dc], bk[0], bk[1]);
                mma16816(sacc[2 * ntp + 1], aq[dc], bk[2], bk[3]);
            }
        }
        #pragma unroll
        for (int nt = 0; nt < 16; nt++) {
            sacc[nt][0] = ex2(sacc[nt][0]);
            sacc[nt][1] = ex2(sacc[nt][1]);
            sacc[nt][2] = ex2(sacc[nt][2]);
            sacc[nt][3] = ex2(sacc[nt][3]);
            lsum0 += sacc[nt][0] + sacc[nt][1];
            lsum1 += sacc[nt][2] + sacc[nt][3];
        }
        #pragma unroll
        for (int kt = 0; kt < 8; kt++) {
            unsigned pa[4];
            pa[0] = pkh2(sacc[2 * kt][0],     sacc[2 * kt][1]);
            pa[1] = pkh2(sacc[2 * kt][2],     sacc[2 * kt][3]);
            pa[2] = pkh2(sacc[2 * kt + 1][0], sacc[2 * kt + 1][1]);
            pa[3] = pkh2(sacc[2 * kt + 1][2], sacc[2 * kt + 1][3]);
            #pragma unroll
            for (int dtp = 0; dtp < 2; dtp++) {
                unsigned bv[4];
                const int row = dtp * 16 + (lane & 7) + ((lane >> 4) & 1) * 8;
                const int col = kt * 16 + ((lane >> 3) & 1) * 8;
                ldsm4(bv, smem_u32(&Vs[buf][row][col]));
                mma16816(oacc[2 * dtp],     pa, bv[0], bv[1]);
                mma16816(oacc[2 * dtp + 1], pa, bv[2], bv[3]);
            }
        }
        __syncthreads();   // all reads of buf done before it is re-issued
    }
    #undef ISSUE_KV

    lsum0 += __shfl_xor_sync(0xffffffff, lsum0, 1);
    lsum0 += __shfl_xor_sync(0xffffffff, lsum0, 2);
    lsum1 += __shfl_xor_sync(0xffffffff, lsum1, 1);
    lsum1 += __shfl_xor_sync(0xffffffff, lsum1, 2);
    const float inv0 = 1.f / lsum0;
    const float inv1 = 1.f / lsum1;

    const int qg = q0 + wq + (lane >> 2);
    #pragma unroll
    for (int dt = 0; dt < 4; dt++) {
        const int d = dt * 8 + (lane & 3) * 2;
        #pragma unroll
        for (int e = 0; e < 2; e++) {
            const long f0 = vflat0 + (long)(d + e) * 1024 + qg;
            g_atth[(f0 >> 20) * C_BSTRIDE + (f0 & 1048575)] =
                __float2half_rn(oacc[dt][e] * inv0);
            const long f1 = f0 + 8;
            g_atth[(f1 >> 20) * C_BSTRIDE + (f1 & 1048575)] =
                __float2half_rn(oacc[dt][2 + e] * inv1);
        }
    }
}

// ---------------- launch -------------------------------------------------------
extern "C" void kernel_launch(void* const* d_in, const int* in_sizes, int n_in,
                              void* d_out, int out_size)
{
    const float* x      = (const float*)d_in[0];
    const float* w_qk   = (const float*)d_in[1];
    const float* s_qk   = (const float*)d_in[2];
    const float* b_qk   = (const float*)d_in[3];
    const float* w_v    = (const float*)d_in[4];
    const float* s_v    = (const float*)d_in[5];
    const float* b_v    = (const float*)d_in[6];
    const float* w_pe   = (const float*)d_in[7];
    const float* s_pe   = (const float*)d_in[8];
    const float* b_pe   = (const float*)d_in[9];
    const float* w_proj = (const float*)d_in[10];
    const float* s_proj = (const float*)d_in[11];
    const float* b_proj = (const float*)d_in[12];
    const float* w_m1   = (const float*)d_in[13];
    const float* s_m1   = (const float*)d_in[14];
    const float* b_m1   = (const float*)d_in[15];
    const float* w_m2   = (const float*)d_in[16];
    const float* s_m2   = (const float*)d_in[17];
    const float* b_m2   = (const float*)d_in[18];
    float* out = (float*)d_out;

    __half *xh, *qkvh, *aph, *x1h, *mh, *wqkvh, *wprojh, *wm1h, *wm2h;
    float *x1, *sqkv, *bqkv;
    cudaGetSymbolAddress((void**)&xh,    g_xh);
    cudaGetSymbolAddress((void**)&qkvh,  g_qkvh);
    cudaGetSymbolAddress((void**)&aph,   g_aph);
    cudaGetSymbolAddress((void**)&x1h,   g_x1h);
    cudaGetSymbolAddress((void**)&mh,    g_mh);
    cudaGetSymbolAddress((void**)&wqkvh, g_wqkvh);
    cudaGetSymbolAddress((void**)&wprojh,g_wprojh);
    cudaGetSymbolAddress((void**)&wm1h,  g_wm1h);
    cudaGetSymbolAddress((void**)&wm2h,  g_wm2h);
    cudaGetSymbolAddress((void**)&x1,    g_x1);
    cudaGetSymbolAddress((void**)&sqkv,  g_sqkvf);
    cudaGetSymbolAddress((void**)&bqkv,  g_bqkvf);

    // 0) fp16 prep
    prep_kernel<<<4096, 256>>>(x, w_qk, w_v, w_proj, w_m1, w_m2,
                               s_qk, b_qk, s_v, b_v);
    // 1) fused qkv GEMM: M=768, fp16 out
    gemm_kernel<<<dim3(32, 6, BSZ), 256>>>(wqkvh, xh, nullptr, sqkv, bqkv,
        nullptr, qkvh, 768, 256, (long)C_BSTRIDE, 0, (long)QKV_BSTRIDE, 0, 0);
    // 2) attention -> g_atth
    attn_kernel<<<dim3(NA / 128, BA * HEADS), 256>>>();
    // 3) dwconv(v) + att add -> g_aph
    dwconv_kernel<<<BSZ * CC, 256>>>(w_pe, s_pe, b_pe);
    // 4) proj: x1 = x + conv1x1(aph, w_proj)
    gemm_kernel<<<dim3(32, 2, BSZ), 256>>>(wprojh, aph, x, s_proj, b_proj,
        x1, x1h, 256, 256, (long)C_BSTRIDE, (long)C_BSTRIDE, (long)C_BSTRIDE,
        (long)C_BSTRIDE, 0);
    // 5) m = silu(conv1x1(x1h, w_m1))
    gemm_kernel<<<dim3(32, 3, BSZ), 256>>>(wm1h, x1h, nullptr, s_m1, b_m1,
        nullptr, mh, MLPD, 256, (long)C_BSTRIDE, 0, (long)MH_BSTRIDE, 0, 1);
    // 6) out = x1 + conv1x1(mh, w_m2)  (K=320 padded)
    gemm_kernel<<<dim3(32, 2, BSZ), 256>>>(wm2h, mh, x1, s_m2, b_m2,
        out, nullptr, 256, MLPD_PAD, (long)MH_BSTRIDE, (long)C_BSTRIDE, 0,
        (long)C_BSTRIDE, 0);
}

// round 17
// speedup vs baseline: 1.6503x; 1.0203x over previous
#include <cuda_runtime.h>
#include <cuda_fp16.h>
#include <math.h>

// Problem constants
#define BSZ   2
#define CC    256
#define NN    4096
#define HEADS 8
#define HD    32
#define BA    8
#define NA    1024
#define MLPD  307
#define MLPD_PAD 320
#define M1_PAD   384

#define QKV_BSTRIDE (768*NN)
#define C_BSTRIDE   (CC*NN)
#define MH_BSTRIDE  (MLPD_PAD*NN)

// ---------------- scratch ----------------------------------------------------
__device__ float  g_x1  [BSZ*CC*NN];
__device__ __half g_xh  [BSZ*CC*NN];
__device__ __half g_qkvh[BSZ*768*NN];
__device__ __half g_atth[BSZ*CC*NN];
__device__ __half g_aph [BSZ*CC*NN];
__device__ __half g_x1h [BSZ*CC*NN];
__device__ __half g_mh  [BSZ*MLPD_PAD*NN];
__device__ __half g_wqkvh[768*256];
__device__ __half g_wprojh[256*256];
__device__ __half g_wm1h[M1_PAD*256];
__device__ __half g_wm2h[256*MLPD_PAD];
__device__ float  g_sqkvf[768];
__device__ float  g_bqkvf[768];

// ---------------- helpers -----------------------------------------------------
__device__ __forceinline__ unsigned hex2(unsigned x) {   // ex2 on packed half2
    unsigned r;
    asm("ex2.approx.f16x2 %0, %1;" : "=r"(r) : "r"(x));
    return r;
}
__device__ __forceinline__ unsigned smem_u32(const void* p) {
    return (unsigned)__cvta_generic_to_shared(p);
}
__device__ __forceinline__ void cpa16(unsigned dst, const __half* src) {
    unsigned long long g = (unsigned long long)__cvta_generic_to_global((const void*)src);
    asm volatile("cp.async.cg.shared.global [%0], [%1], 16;" :: "r"(dst), "l"(g) : "memory");
}
__device__ __forceinline__ void ldsm4(unsigned* r, unsigned addr) {
    asm volatile("ldmatrix.sync.aligned.m8n8.x4.shared.b16 {%0,%1,%2,%3}, [%4];"
        : "=r"(r[0]), "=r"(r[1]), "=r"(r[2]), "=r"(r[3]) : "r"(addr));
}
__device__ __forceinline__ void ldsm4t(unsigned* r, unsigned addr) {
    asm volatile("ldmatrix.sync.aligned.m8n8.x4.trans.shared.b16 {%0,%1,%2,%3}, [%4];"
        : "=r"(r[0]), "=r"(r[1]), "=r"(r[2]), "=r"(r[3]) : "r"(addr));
}
__device__ __forceinline__ void mma16816(float* c, const unsigned* a,
                                         unsigned b0, unsigned b1) {
    asm volatile("mma.sync.aligned.m16n8k16.row.col.f32.f16.f16.f32 "
        "{%0,%1,%2,%3},{%4,%5,%6,%7},{%8,%9},{%0,%1,%2,%3};"
        : "+f"(c[0]), "+f"(c[1]), "+f"(c[2]), "+f"(c[3])
        : "r"(a[0]), "r"(a[1]), "r"(a[2]), "r"(a[3]), "r"(b0), "r"(b1));
}
__device__ __forceinline__ void mma16816h(unsigned* c, const unsigned* a,
                                          unsigned b0, unsigned b1) {
    asm volatile("mma.sync.aligned.m16n8k16.row.col.f16.f16.f16.f16 "
        "{%0,%1},{%2,%3,%4,%5},{%6,%7},{%0,%1};"
        : "+r"(c[0]), "+r"(c[1])
        : "r"(a[0]), "r"(a[1]), "r"(a[2]), "r"(a[3]), "r"(b0), "r"(b1));
}

// ---------------- prep: fp16 conversions + padding ----------------------------
__global__ void prep_kernel(const float* __restrict__ x,
                            const float* __restrict__ w_qk, const float* __restrict__ w_v,
                            const float* __restrict__ w_proj,
                            const float* __restrict__ w_m1, const float* __restrict__ w_m2,
                            const float* __restrict__ s_qk, const float* __restrict__ b_qk,
                            const float* __restrict__ s_v,  const float* __restrict__ b_v)
{
    const int S0 = BSZ*CC*NN;
    const int S1 = 768*256;
    const int S2 = 256*256;
    const int S3 = M1_PAD*256;
    const int S4 = 256*MLPD_PAD;
    const int S5 = BSZ*(MLPD_PAD-MLPD)*NN;
    const int S6 = 768;
    const int TOT = S0+S1+S2+S3+S4+S5+S6+S6;
    for (int i = blockIdx.x*blockDim.x + threadIdx.x; i < TOT; i += gridDim.x*blockDim.x) {
        int idx = i;
        if (idx < S0) { g_xh[idx] = __float2half_rn(x[idx]); continue; }
        idx -= S0;
        if (idx < S1) {
            g_wqkvh[idx] = __float2half_rn(idx < 512*256 ? w_qk[idx] : w_v[idx-512*256]);
            continue;
        }
        idx -= S1;
        if (idx < S2) { g_wprojh[idx] = __float2half_rn(w_proj[idx]); continue; }
        idx -= S2;
        if (idx < S3) {
            const int r = idx >> 8;
            g_wm1h[idx] = __float2half_rn(r < MLPD ? w_m1[idx] : 0.f);
            continue;
        }
        idx -= S3;
        if (idx < S4) {
            const int r = idx / MLPD_PAD, c = idx % MLPD_PAD;
            g_wm2h[idx] = __float2half_rn(c < MLPD ? w_m2[r*MLPD + c] : 0.f);
            continue;
        }
        idx -= S4;
        if (idx < S5) {
            const int b  = idx / ((MLPD_PAD-MLPD)*NN);
            const int rr = idx % ((MLPD_PAD-MLPD)*NN);
            g_mh[(long)b*MH_BSTRIDE + MLPD*NN + rr] = __float2half_rn(0.f);
            continue;
        }
        idx -= S5;
        if (idx < S6) { g_sqkvf[idx] = idx < 512 ? s_qk[idx] : s_v[idx-512]; continue; }
        idx -= S6;
        g_bqkvf[idx] = idx < 512 ? b_qk[idx] : b_v[idx-512];
    }
}

// ---- conv1x1 GEMM via HMMA + cp.async (identical to R14 — verified) ----------
#define BKK 32
#define AP  (BKK + 8)
#define BP  (128 + 8)

__global__ __launch_bounds__(256, 2)
void gemm_kernel(const __half* __restrict__ Ag_,
                 const __half* __restrict__ Bg_,
                 const float* __restrict__ res,
                 const float* __restrict__ sc,
                 const float* __restrict__ bi,
                 float* __restrict__ Cf_,
                 __half* __restrict__ Ch_,
                 int M, int K,
                 long sB, long sCf, long sCh, long sR, int epi)
{
    __shared__ __align__(16) __half As[2][128][AP];
    __shared__ __align__(16) __half Bs[2][BKK][BP];

    const int b = blockIdx.z;
    const __half* Ag = Ag_;
    const __half* Bg = Bg_ + (long)b * sB;
    const float*  Rb = res ? (res + (long)b * sR) : nullptr;
    float*  Cf = Cf_ ? (Cf_ + (long)b * sCf) : nullptr;
    __half* Ch = Ch_ ? (Ch_ + (long)b * sCh) : nullptr;

    const int m0 = blockIdx.y * 128;
    const int n0 = blockIdx.x * 128;
    const int tid  = threadIdx.x;
    const int lane = tid & 31;
    const int wid  = tid >> 5;
    const int wm = (wid >> 2) * 64;
    const int wn = (wid & 3) * 32;

    const int nkt = K / BKK;

    float acc[4][4][4] = {};

    #define ISSUE(KT)                                                          \
    {                                                                          \
        const int k0 = (KT) * BKK;                                             \
        const int st = (KT) & 1;                                               \
        const __half* ap = Ag + (long)(m0 + (tid >> 1)) * K + k0 + (tid & 1) * 16; \
        cpa16(smem_u32(&As[st][tid >> 1][(tid & 1) * 16]), ap);                \
        cpa16(smem_u32(&As[st][tid >> 1][(tid & 1) * 16 + 8]), ap + 8);        \
        const __half* bp = Bg + (long)(k0 + (tid >> 3)) * NN + n0 + (tid & 7) * 16; \
        cpa16(smem_u32(&Bs[st][tid >> 3][(tid & 7) * 16]), bp);                \
        cpa16(smem_u32(&Bs[st][tid >> 3][(tid & 7) * 16 + 8]), bp + 8);        \
        asm volatile("cp.async.commit_group;" ::: "memory");                   \
    }

    ISSUE(0)

    for (int kt = 0; kt < nkt; kt++) {
        if (kt + 1 < nkt) {
            ISSUE(kt + 1)
            asm volatile("cp.async.wait_group 1;" ::: "memory");
        } else {
            asm volatile("cp.async.wait_group 0;" ::: "memory");
        }
        __syncthreads();
        const int buf = kt & 1;
        #pragma unroll
        for (int ks = 0; ks < BKK; ks += 16) {
            unsigned afr[4][4], bfr[2][4];
            #pragma unroll
            for (int mi = 0; mi < 4; mi++) {
                const unsigned addr = smem_u32(
                    &As[buf][wm + mi * 16 + (lane & 15)][ks + (lane >> 4) * 8]);
                ldsm4(afr[mi], addr);
            }
            #pragma unroll
            for (int g = 0; g < 2; g++) {
                const int row = ks + (lane & 15);
                const int col = wn + g * 16 + ((lane >> 4) * 8);
                ldsm4t(bfr[g], smem_u32(&Bs[buf][row][col]));
            }
            #pragma unroll
            for (int mi = 0; mi < 4; mi++)
                #pragma unroll
                for (int g = 0; g < 2; g++) {
                    mma16816(acc[mi][2 * g],     afr[mi], bfr[g][0], bfr[g][1]);
                    mma16816(acc[mi][2 * g + 1], afr[mi], bfr[g][2], bfr[g][3]);
                }
        }
        __syncthreads();
    }
    #undef ISSUE

    #pragma unroll
    for (int mi = 0; mi < 4; mi++) {
        #pragma unroll
        for (int hh = 0; hh < 2; hh++) {
            const int m = m0 + wm + mi * 16 + (lane >> 2) + hh * 8;
            if (m >= M) continue;
            const float scl = sc[m], bia = bi[m];
            #pragma unroll
            for (int ni = 0; ni < 4; ni++) {
                float v0 = acc[mi][ni][2 * hh]     * scl + bia;
                float v1 = acc[mi][ni][2 * hh + 1] * scl + bia;
                if (epi == 1) {
                    v0 = v0 / (1.f + __expf(-v0));
                    v1 = v1 / (1.f + __expf(-v1));
                }
                const int n = n0 + wn + ni * 8 + (lane & 3) * 2;
                const long base = (long)m * NN + n;
                if (Rb) {
                    const float2 r = *(const float2*)(Rb + base);
                    v0 += r.x; v1 += r.y;
                }
                if (Cf) *(float2*)(Cf + base) = make_float2(v0, v1);
                if (Ch) *(__half2*)(Ch + base) = __floats2half2_rn(v0, v1);
            }
        }
    }
}

// ---- depthwise 3x3, smem-tiled (identical to R15 — verified) -----------------
__global__ __launch_bounds__(256)
void dwconv_kernel(const float* __restrict__ w_pe,
                   const float* __restrict__ s,
                   const float* __restrict__ bi)
{
    __shared__ __align__(16) __half plane[4096];

    const int bc = blockIdx.x;
    const int b = bc >> 8, c = bc & 255;
    const int tid = threadIdx.x;

    const __half* src = g_qkvh + (long)b * QKV_BSTRIDE + (long)(512 + c) * NN;
    {
        const int o = tid * 16;
        *(uint4*)&plane[o]     = *(const uint4*)(src + o);
        *(uint4*)&plane[o + 8] = *(const uint4*)(src + o + 8);
    }

    const float sc = s[c];
    float wk[9];
    #pragma unroll
    for (int j = 0; j < 9; j++) wk[j] = w_pe[c * 9 + j] * sc;
    const float bia = bi[c];

    __syncthreads();

    const int h  = tid >> 2;
    const int w0 = (tid & 3) * 16;

    float r[3][18];
    #pragma unroll
    for (int rr = 0; rr < 3; rr++) {
        const int row = h + rr - 1;
        if (row < 0 || row >= 64) {
            #pragma unroll
            for (int j = 0; j < 18; j++) r[rr][j] = 0.f;
        } else {
            const __half* p = &plane[row * 64];
            #pragma unroll
            for (int j = 0; j < 18; j++) {
                const int col = w0 - 1 + j;
                r[rr][j] = (col >= 0 && col < 64) ? __half2float(p[col]) : 0.f;
            }
        }
    }

    const long o = (long)b * C_BSTRIDE + (long)c * NN + h * 64 + w0;
    uint4 a0 = *(const uint4*)(g_atth + o);
    uint4 a1 = *(const uint4*)(g_atth + o + 8);
    const __half2* ah0 = (const __half2*)&a0;
    const __half2* ah1 = (const __half2*)&a1;

    uint4 o0, o1;
    __half2* oh0 = (__half2*)&o0;
    __half2* oh1 = (__half2*)&o1;

    #pragma unroll
    for (int i = 0; i < 16; i++) {
        float acc = bia;
        #pragma unroll
        for (int rr = 0; rr < 3; rr++) {
            acc = fmaf(r[rr][i],     wk[rr * 3 + 0], acc);
            acc = fmaf(r[rr][i + 1], wk[rr * 3 + 1], acc);
            acc = fmaf(r[rr][i + 2], wk[rr * 3 + 2], acc);
        }
        const float2 av = (i < 8) ? __half22float2(ah0[i >> 1])
                                  : __half22float2(ah1[(i - 8) >> 1]);
        const float att = (i & 1) ? av.y : av.x;
        __half hv = __float2half_rn(acc + att);
        if (i < 8) ((__half*)oh0)[i] = hv;
        else       ((__half*)oh1)[i - 8] = hv;
    }
    *(uint4*)(g_aph + o)     = o0;
    *(uint4*)(g_aph + o + 8) = o1;
}

// ---- area attention: HMMA, f16 scores, f16x2 exp, lsum-by-MMA ----------------
#define PITCH 136

__global__ __launch_bounds__(256)
void attn_kernel()
{
    __shared__ __align__(16) __half Qs[32][PITCH];
    __shared__ __align__(16) __half Ks[2][32][PITCH];
    __shared__ __align__(16) __half Vs[2][32][PITCH];

    const int ba = blockIdx.y >> 3;
    const int h  = blockIdx.y & 7;
    const int q0 = blockIdx.x * 128;
    const int tid  = threadIdx.x;
    const int lane = tid & 31;
    const int wid  = tid >> 5;
    const int wq   = wid * 16;

    const float scale = 0.17677669529663687f * 1.4426950408889634f;

    const long qflat0 = (long)ba * 524288 + (long)(h * HD) * 1024;
    const long kflat0 = qflat0 + 256 * 1024;
    const long vflat0 = (long)ba * 262144 + (long)(h * HD) * 1024;

    const int fd = tid >> 3;
    const int fg = (tid & 7) * 16;

    const long fk0 = kflat0 + (long)fd * 1024 + fg;
    const __half* kp = &g_qkvh[(fk0 >> 21) * QKV_BSTRIDE + (fk0 & 2097151)];
    const long fv0 = vflat0 + (long)fd * 1024 + fg;
    const __half* vp = &g_qkvh[(fv0 >> 20) * QKV_BSTRIDE + 512 * NN + (fv0 & 1048575)];

    #define ISSUE_KV(CH)                                                       \
    {                                                                          \
        const int st = (CH) & 1;                                               \
        const int off = (CH) * 128;                                            \
        cpa16(smem_u32(&Ks[st][fd][fg]),     kp + off);                        \
        cpa16(smem_u32(&Ks[st][fd][fg + 8]), kp + off + 8);                    \
        cpa16(smem_u32(&Vs[st][fd][fg]),     vp + off);                        \
        cpa16(smem_u32(&Vs[st][fd][fg + 8]), vp + off + 8);                    \
        asm volatile("cp.async.commit_group;" ::: "memory");                   \
    }

    ISSUE_KV(0)

    // Q fill (once, scaled)
    {
        const long f = qflat0 + (long)fd * 1024 + q0 + fg;
        const __half* src = &g_qkvh[(f >> 21) * QKV_BSTRIDE + (f & 2097151)];
        uint4 u0 = *(const uint4*)src;
        uint4 u1 = *(const uint4*)(src + 8);
        __half2* p0 = (__half2*)&u0;
        __half2* p1 = (__half2*)&u1;
        #pragma unroll
        for (int j = 0; j < 4; j++) {
            float2 f0 = __half22float2(p0[j]);
            p0[j] = __floats2half2_rn(f0.x * scale, f0.y * scale);
            float2 f1 = __half22float2(p1[j]);
            p1[j] = __floats2half2_rn(f1.x * scale, f1.y * scale);
        }
        *(uint4*)&Qs[fd][fg]     = u0;
        *(uint4*)&Qs[fd][fg + 8] = u1;
    }
    __syncthreads();

    unsigned aq[2][4];
    #pragma unroll
    for (int dc = 0; dc < 2; dc++) {
        const int row = dc * 16 + (lane & 7) + ((lane >> 4) & 1) * 8;
        const int col = wq + ((lane >> 3) & 1) * 8;
        ldsm4t(aq[dc], smem_u32(&Qs[row][col]));
    }

    // ones-column b-frag for row-sum MMA: B[k][0] = 1, other cols 0
    const unsigned ones_b = (lane < 4) ? 0x3C003C00u : 0u;

    float oacc[4][4] = {};
    float ssum[4] = {};     // c-frag: col0 (at lane%4==0) = row sums

    for (int ch = 0; ch < 8; ch++) {
        asm volatile("cp.async.wait_group 0;" ::: "memory");
        __syncthreads();
        if (ch + 1 < 8) ISSUE_KV(ch + 1)
        const int buf = ch & 1;

        // S = Q^T K, fp16 accumulation (c-frag pair == P a-frag layout)
        unsigned sacc[16][2];
        #pragma unroll
        for (int nt = 0; nt < 16; nt++) { sacc[nt][0] = 0u; sacc[nt][1] = 0u; }
        #pragma unroll
        for (int dc = 0; dc < 2; dc++) {
            #pragma unroll
            for (int ntp = 0; ntp < 8; ntp++) {
                unsigned bk[4];
                const int row = dc * 16 + (lane & 7) + ((lane >> 3) & 1) * 8;
                const int col = ntp * 16 + ((lane >> 4) & 1) * 8;
                ldsm4t(bk, smem_u32(&Ks[buf][row][col]));
                mma16816h(sacc[2 * ntp],     aq[dc], bk[0], bk[1]);
                mma16816h(sacc[2 * ntp + 1], aq[dc], bk[2], bk[3]);
            }
        }
        // P = 2^S, packed half2 exp (MUFU halved)
        #pragma unroll
        for (int nt = 0; nt < 16; nt++) {
            sacc[nt][0] = hex2(sacc[nt][0]);
            sacc[nt][1] = hex2(sacc[nt][1]);
        }
        // out += P V^T ; lsum += P * ones
        #pragma unroll
        for (int kt = 0; kt < 8; kt++) {
            unsigned pa[4];
            pa[0] = sacc[2 * kt][0];
            pa[1] = sacc[2 * kt][1];
            pa[2] = sacc[2 * kt + 1][0];
            pa[3] = sacc[2 * kt + 1][1];
            mma16816(ssum, pa, ones_b, ones_b);
            #pragma unroll
            for (int dtp = 0; dtp < 2; dtp++) {
                unsigned bv[4];
                const int row = dtp * 16 + (lane & 7) + ((lane >> 4) & 1) * 8;
                const int col = kt * 16 + ((lane >> 3) & 1) * 8;
                ldsm4(bv, smem_u32(&Vs[buf][row][col]));
                mma16816(oacc[2 * dtp],     pa, bv[0], bv[1]);
                mma16816(oacc[2 * dtp + 1], pa, bv[2], bv[3]);
            }
        }
        __syncthreads();
    }
    #undef ISSUE_KV

    // row sums live in col 0 => quad leader's ssum[0] (row) / ssum[2] (row+8)
    const float lsum0 = __shfl_sync(0xffffffff, ssum[0], lane & ~3);
    const float lsum1 = __shfl_sync(0xffffffff, ssum[2], lane & ~3);
    const float inv0 = 1.f / lsum0;
    const float inv1 = 1.f / lsum1;

    const int qg = q0 + wq + (lane >> 2);
    #pragma unroll
    for (int dt = 0; dt < 4; dt++) {
        const int d = dt * 8 + (lane & 3) * 2;
        #pragma unroll
        for (int e = 0; e < 2; e++) {
            const long f0 = vflat0 + (long)(d + e) * 1024 + qg;
            g_atth[(f0 >> 20) * C_BSTRIDE + (f0 & 1048575)] =
                __float2half_rn(oacc[dt][e] * inv0);
            const long f1 = f0 + 8;
            g_atth[(f1 >> 20) * C_BSTRIDE + (f1 & 1048575)] =
                __float2half_rn(oacc[dt][2 + e] * inv1);
        }
    }
}

// ---------------- launch -------------------------------------------------------
extern "C" void kernel_launch(void* const* d_in, const int* in_sizes, int n_in,
                              void* d_out, int out_size)
{
    const float* x      = (const float*)d_in[0];
    const float* w_qk   = (const float*)d_in[1];
    const float* s_qk   = (const float*)d_in[2];
    const float* b_qk   = (const float*)d_in[3];
    const float* w_v    = (const float*)d_in[4];
    const float* s_v    = (const float*)d_in[5];
    const float* b_v    = (const float*)d_in[6];
    const float* w_pe   = (const float*)d_in[7];
    const float* s_pe   = (const float*)d_in[8];
    const float* b_pe   = (const float*)d_in[9];
    const float* w_proj = (const float*)d_in[10];
    const float* s_proj = (const float*)d_in[11];
    const float* b_proj = (const float*)d_in[12];
    const float* w_m1   = (const float*)d_in[13];
    const float* s_m1   = (const float*)d_in[14];
    const float* b_m1   = (const float*)d_in[15];
    const float* w_m2   = (const float*)d_in[16];
    const float* s_m2   = (const float*)d_in[17];
    const float* b_m2   = (const float*)d_in[18];
    float* out = (float*)d_out;

    __half *xh, *qkvh, *aph, *x1h, *mh, *wqkvh, *wprojh, *wm1h, *wm2h;
    float *x1, *sqkv, *bqkv;
    cudaGetSymbolAddress((void**)&xh,    g_xh);
    cudaGetSymbolAddress((void**)&qkvh,  g_qkvh);
    cudaGetSymbolAddress((void**)&aph,   g_aph);
    cudaGetSymbolAddress((void**)&x1h,   g_x1h);
    cudaGetSymbolAddress((void**)&mh,    g_mh);
    cudaGetSymbolAddress((void**)&wqkvh, g_wqkvh);
    cudaGetSymbolAddress((void**)&wprojh,g_wprojh);
    cudaGetSymbolAddress((void**)&wm1h,  g_wm1h);
    cudaGetSymbolAddress((void**)&wm2h,  g_wm2h);
    cudaGetSymbolAddress((void**)&x1,    g_x1);
    cudaGetSymbolAddress((void**)&sqkv,  g_sqkvf);
    cudaGetSymbolAddress((void**)&bqkv,  g_bqkvf);

    // 0) fp16 prep
    prep_kernel<<<4096, 256>>>(x, w_qk, w_v, w_proj, w_m1, w_m2,
                               s_qk, b_qk, s_v, b_v);
    // 1) fused qkv GEMM: M=768, fp16 out
    gemm_kernel<<<dim3(32, 6, BSZ), 256>>>(wqkvh, xh, nullptr, sqkv, bqkv,
        nullptr, qkvh, 768, 256, (long)C_BSTRIDE, 0, (long)QKV_BSTRIDE, 0, 0);
    // 2) attention -> g_atth
    attn_kernel<<<dim3(NA / 128, BA * HEADS), 256>>>();
    // 3) dwconv(v) + att add -> g_aph
    dwconv_kernel<<<BSZ * CC, 256>>>(w_pe, s_pe, b_pe);
    // 4) proj: x1 = x + conv1x1(aph, w_proj)
    gemm_kernel<<<dim3(32, 2, BSZ), 256>>>(wprojh, aph, x, s_proj, b_proj,
        x1, x1h, 256, 256, (long)C_BSTRIDE, (long)C_BSTRIDE, (long)C_BSTRIDE,
        (long)C_BSTRIDE, 0);
    // 5) m = silu(conv1x1(x1h, w_m1))
    gemm_kernel<<<dim3(32, 3, BSZ), 256>>>(wm1h, x1h, nullptr, s_m1, b_m1,
        nullptr, mh, MLPD, 256, (long)C_BSTRIDE, 0, (long)MH_BSTRIDE, 0, 1);
    // 6) out = x1 + conv1x1(mh, w_m2)  (K=320 padded)
    gemm_kernel<<<dim3(32, 2, BSZ), 256>>>(wm2h, mh, x1, s_m2, b_m2,
        out, nullptr, 256, MLPD_PAD, (long)MH_BSTRIDE, (long)C_BSTRIDE, 0,
        (long)C_BSTRIDE, 0);
}